// round 12
// baseline (speedup 1.0000x reference)
#include <cuda_runtime.h>
#include <cuda_bf16.h>
#include <cstdint>
#include <math.h>

// ---------------------------------------------------------------------------
// Fixed problem shape:
//   BATCH=2, SEQLEN=1024, D_MODEL=1024, D_INNER=2048, DT_RANK=128, D_STATE=16,
//   D_CONV=4. Tokens NT = 2048.
// ---------------------------------------------------------------------------
#define DI      2048
#define DM      1024
#define LSEQ    1024
#define NT      2048
#define NSTATE  16
#define DTR     128
#define XPN     160      // DT_RANK + 2*D_STATE

// ----------------------- device scratch (no mallocs) -----------------------
__device__ float g_xz   [NT * 2 * DI];      // in_proj out: [x_in | z]
__device__ float g_u    [NT * DI];          // silu(conv(x_in))
__device__ float g_xdbl [NT * XPN];         // u @ W_xproj
__device__ float g_dt   [NT * DI];          // softplus(...)
__device__ float g_ys   [NT * DI];          // gated scan output
__device__ float g_A    [DI * NSTATE];      // A = -exp(A_log)
__device__ float g_pxd  [8 * NT * XPN];     // split-K partials (xproj)
__device__ float g_pout [2 * NT * DM];      // split-K partials (out)

// ----------------------- misc device helpers -------------------------------
__device__ __forceinline__ float softplus_f(float x) {
    if (x > 20.0f) return x;
    return log1pf(__expf(x));
}

// ----------------------- tf32 tensor helpers -------------------------------
__device__ __forceinline__ void split_tf32(float v, unsigned& hi, unsigned& lo) {
    unsigned h;
    asm("cvt.rna.tf32.f32 %0, %1;" : "=r"(h) : "f"(v));
    float r = v - __uint_as_float(h);
    unsigned l;
    asm("cvt.rna.tf32.f32 %0, %1;" : "=r"(l) : "f"(r));
    hi = h; lo = l;
}
__device__ __forceinline__ void split_store4(float4 v, unsigned* hi, unsigned* lo) {
    unsigned h0, l0, h1, l1, h2, l2, h3, l3;
    split_tf32(v.x, h0, l0); split_tf32(v.y, h1, l1);
    split_tf32(v.z, h2, l2); split_tf32(v.w, h3, l3);
    *(uint4*)hi = make_uint4(h0, h1, h2, h3);
    *(uint4*)lo = make_uint4(l0, l1, l2, l3);
}
__device__ __forceinline__ void mma_tf32(float* d, const unsigned* a, const unsigned* b) {
    asm volatile(
        "mma.sync.aligned.m16n8k8.row.col.f32.tf32.tf32.f32 "
        "{%0,%1,%2,%3}, {%4,%5,%6,%7}, {%8,%9}, {%0,%1,%2,%3};\n"
        : "+f"(d[0]), "+f"(d[1]), "+f"(d[2]), "+f"(d[3])
        : "r"(a[0]), "r"(a[1]), "r"(a[2]), "r"(a[3]), "r"(b[0]), "r"(b[1]));
}

// SMEM partition constants (in 4-byte words)
#define AS_W  (128 * 20)     // 2560 per buffer (stride-20 pad: conflict-free)
#define BS_W  (16 * 136)     // 2176 per buffer (stride-136 pad: conflict-free)
#define TG_SMEM_BYTES ((2 * AS_W * 2 + 2 * BS_W * 2) * 4)   // 75776

// ---------------------------------------------------------------------------
// Tensor-core tf32 GEMM, 3-term compensation, hi/lo PRE-SPLIT in SMEM.
//   C[M,N] = A[M,K] @ B[K,N], row-major fp32 in/out.
//   128x128 block tile, BK=16, 256 threads = 8 warps (4x2), warp = 32x64.
//   Requires M%128==0, Kslice%16==0, N%8==0 (GUARDN=1 allows N not mult of 128).
//   EPI==1 -> softplus(acc + bias[col]). blockIdx.z = split-K slice.
// ---------------------------------------------------------------------------
template <int EPI, int GUARDN>
__global__ void __launch_bounds__(256, 2)
tgemm2(const float* __restrict__ A, const float* __restrict__ B,
       float* __restrict__ C, int M, int N, int K,
       int lda, int ldb, int ldc,
       int Kslice, long long cSliceStride, const float* __restrict__ bias)
{
    extern __shared__ unsigned smem_u[];
    unsigned* AsH = smem_u;                 // [2][AS_W]
    unsigned* AsL = AsH + 2 * AS_W;
    unsigned* BsH = AsL + 2 * AS_W;         // [2][BS_W]
    unsigned* BsL = BsH + 2 * BS_W;

    const int tid  = threadIdx.x;
    const int lane = tid & 31;
    const int wid  = tid >> 5;
    const int wm   = wid & 3;               // 4 warps in M
    const int wn   = wid >> 2;               // 2 warps in N
    const int bx = blockIdx.x, by = blockIdx.y, bz = blockIdx.z;

    C += (long long)bz * cSliceStride;
    const int k0 = bz * Kslice;
    const int KT = Kslice >> 4;

    // global load mapping: A 128x16 (2 float4/thread), B 16x128 (2 float4/thread)
    const int aRow = tid >> 1;
    const int aK   = (tid & 1) * 8;
    const int bRow = tid >> 4;
    const int bCol = (tid & 15) * 8;

    const int  gBCol = bx * 128 + bCol;
    const bool bOk   = !GUARDN || (gBCol < N);   // N%8==0 -> covers both float4

    const float* Ag = A + (long long)(by * 128 + aRow) * lda + k0 + aK;
    const float* Bg = B + (long long)(k0 + bRow) * ldb + gBCol;

    float acc[2][8][4];
#pragma unroll
    for (int mt = 0; mt < 2; mt++)
#pragma unroll
        for (int nt = 0; nt < 8; nt++)
#pragma unroll
            for (int j = 0; j < 4; j++) acc[mt][nt][j] = 0.f;

    // preload tile 0 into buffer 0 (split at store time)
    {
        float4 pa0 = *(const float4*)(Ag);
        float4 pa1 = *(const float4*)(Ag + 4);
        float4 pb0 = bOk ? *(const float4*)(Bg)     : make_float4(0,0,0,0);
        float4 pb1 = bOk ? *(const float4*)(Bg + 4) : make_float4(0,0,0,0);
        const int ai = aRow * 20 + aK;
        const int bi = bRow * 136 + bCol;
        split_store4(pa0, &AsH[ai],     &AsL[ai]);
        split_store4(pa1, &AsH[ai + 4], &AsL[ai + 4]);
        split_store4(pb0, &BsH[bi],     &BsL[bi]);
        split_store4(pb1, &BsH[bi + 4], &BsL[bi + 4]);
    }

    int cur = 0;
    const int frow = lane >> 2;      // 0..7
    const int fcol = lane & 3;       // 0..3

    for (int kt = 0; kt < KT; ++kt) {
        __syncthreads();

        float4 pa0, pa1, pb0, pb1;
        const bool more = (kt + 1 < KT);
        if (more) {
            const float* Ag2 = Ag + (kt + 1) * 16;
            const float* Bg2 = Bg + (long long)(kt + 1) * 16 * ldb;
            pa0 = *(const float4*)(Ag2);
            pa1 = *(const float4*)(Ag2 + 4);
            pb0 = bOk ? *(const float4*)(Bg2)     : make_float4(0,0,0,0);
            pb1 = bOk ? *(const float4*)(Bg2 + 4) : make_float4(0,0,0,0);
        }

        const unsigned* ah_s = AsH + cur * AS_W;
        const unsigned* al_s = AsL + cur * AS_W;
        const unsigned* bh_s = BsH + cur * BS_W;
        const unsigned* bl_s = BsL + cur * BS_W;

#pragma unroll
        for (int ks = 0; ks < 2; ++ks) {
            const int c = ks * 8 + fcol;
            unsigned ah[2][4], al[2][4];
#pragma unroll
            for (int mt = 0; mt < 2; mt++) {
                const int r = wm * 32 + mt * 16 + frow;
                const int i0 = r * 20 + c;
                ah[mt][0] = ah_s[i0];            al[mt][0] = al_s[i0];
                ah[mt][1] = ah_s[i0 + 160];      al[mt][1] = al_s[i0 + 160];   // +8 rows
                ah[mt][2] = ah_s[i0 + 4];        al[mt][2] = al_s[i0 + 4];
                ah[mt][3] = ah_s[i0 + 164];      al[mt][3] = al_s[i0 + 164];
            }
#pragma unroll
            for (int nt = 0; nt < 8; nt++) {
                const int col = wn * 64 + nt * 8 + frow;
                unsigned bh[2], bl[2];
                bh[0] = bh_s[c * 136 + col];        bl[0] = bl_s[c * 136 + col];
                bh[1] = bh_s[(c + 4) * 136 + col];  bl[1] = bl_s[(c + 4) * 136 + col];
#pragma unroll
                for (int mt = 0; mt < 2; mt++) {
                    mma_tf32(acc[mt][nt], ah[mt], bh);   // hi*hi
                    mma_tf32(acc[mt][nt], al[mt], bh);   // lo*hi
                    mma_tf32(acc[mt][nt], ah[mt], bl);   // hi*lo
                }
            }
        }

        if (more) {
            const int nb = cur ^ 1;
            const int ai = aRow * 20 + aK;
            const int bi = bRow * 136 + bCol;
            split_store4(pa0, &AsH[nb * AS_W + ai],     &AsL[nb * AS_W + ai]);
            split_store4(pa1, &AsH[nb * AS_W + ai + 4], &AsL[nb * AS_W + ai + 4]);
            split_store4(pb0, &BsH[nb * BS_W + bi],     &BsL[nb * BS_W + bi]);
            split_store4(pb1, &BsH[nb * BS_W + bi + 4], &BsL[nb * BS_W + bi + 4]);
            cur = nb;
        }
    }

    // epilogue
    const int rbase = by * 128 + wm * 32;
    const int cbase = bx * 128 + wn * 64;
#pragma unroll
    for (int mt = 0; mt < 2; mt++) {
#pragma unroll
        for (int nt = 0; nt < 8; nt++) {
            const int r  = rbase + mt * 16 + frow;
            const int cc = cbase + nt * 8 + fcol * 2;
            if (GUARDN && cc >= N) continue;
            float v0 = acc[mt][nt][0], v1 = acc[mt][nt][1];
            float v2 = acc[mt][nt][2], v3 = acc[mt][nt][3];
            if (EPI == 1) {
                const float b0 = bias[cc], b1 = bias[cc + 1];
                v0 = softplus_f(v0 + b0); v1 = softplus_f(v1 + b1);
                v2 = softplus_f(v2 + b0); v3 = softplus_f(v3 + b1);
            }
            *(float2*)&C[(long long)r * ldc + cc]       = make_float2(v0, v1);
            *(float2*)&C[(long long)(r + 8) * ldc + cc] = make_float2(v2, v3);
        }
    }
}

// ---------------------------------------------------------------------------
// A = -exp(A_log)
// ---------------------------------------------------------------------------
__global__ void prep_kernel(const float* __restrict__ A_log) {
    const int i = blockIdx.x * 256 + threadIdx.x;
    g_A[i] = -expf(A_log[i]);
}

// ---------------------------------------------------------------------------
// depthwise causal conv1d (kw=4) + SiLU; input = g_xz[:, :DI], out = g_u
// ---------------------------------------------------------------------------
__global__ void __launch_bounds__(256)
conv_silu_kernel(const float* __restrict__ ck, const float* __restrict__ cb) {
    const int idx = blockIdx.x * 256 + threadIdx.x;   // < NT*DI
    const int d = idx & (DI - 1);
    const int t = idx >> 11;                          // token = b*L + l
    const int l = t & (LSEQ - 1);
    float acc = cb[d];
#pragma unroll
    for (int k = 0; k < 4; k++) {
        const int ll = l + k - 3;
        if (ll >= 0)
            acc = fmaf(g_xz[(long long)(t + k - 3) * (2 * DI) + d],
                       ck[k * DI + d], acc);
    }
    g_u[idx] = acc * (1.0f / (1.0f + __expf(-acc)));
}

// ---------------------------------------------------------------------------
// split-K reductions
// ---------------------------------------------------------------------------
__global__ void reduce8_kernel() {
    const int i = blockIdx.x * 256 + threadIdx.x;     // NT*XPN
    float s = 0.f;
#pragma unroll
    for (int k = 0; k < 8; k++) s += g_pxd[(long long)k * (NT * XPN) + i];
    g_xdbl[i] = s;
}
__global__ void reduce2_kernel(float* __restrict__ out) {
    const int i = blockIdx.x * 256 + threadIdx.x;     // NT*DM
    out[i] = g_pout[i] + g_pout[NT * DM + i];
}

// ---------------------------------------------------------------------------
// selective scan: 8 threads per channel (2 states each), shfl reduce,
// one-step prefetch; fused skip (u*D) and gating (* silu(z)).
// grid: (DI/32, BATCH), block 256 (32 channels/block) -> single wave (128 blocks).
// ---------------------------------------------------------------------------
__global__ void __launch_bounds__(256)
scan_kernel(const float* __restrict__ Dp) {
    const int tid = threadIdx.x;
    const int sub = tid & 7;                          // state pair index
    const int dd  = blockIdx.x * 32 + (tid >> 3);     // channel
    const long long t0 = (long long)blockIdx.y * LSEQ;

    const float a0 = g_A[dd * NSTATE + sub * 2 + 0];
    const float a1 = g_A[dd * NSTATE + sub * 2 + 1];
    const float Dv = Dp[dd];
    float h0 = 0.f, h1 = 0.f;

    // prefetch step 0
    float  dt_n = g_dt[t0 * DI + dd];
    float  u_n  = g_u [t0 * DI + dd];
    float  z_n  = g_xz[t0 * (2 * DI) + DI + dd];
    float2 B_n  = *(const float2*)&g_xdbl[t0 * XPN + DTR + sub * 2];
    float2 C_n  = *(const float2*)&g_xdbl[t0 * XPN + DTR + NSTATE + sub * 2];

    for (int l = 0; l < LSEQ; ++l) {
        const float  dtc = dt_n, uc = u_n, zc = z_n;
        const float2 Bc = B_n, Cc = C_n;
        if (l + 1 < LSEQ) {
            const long long tn = t0 + l + 1;
            dt_n = g_dt[tn * DI + dd];
            u_n  = g_u [tn * DI + dd];
            z_n  = g_xz[tn * (2 * DI) + DI + dd];
            B_n  = *(const float2*)&g_xdbl[tn * XPN + DTR + sub * 2];
            C_n  = *(const float2*)&g_xdbl[tn * XPN + DTR + NSTATE + sub * 2];
        }
        const float dtu = dtc * uc;
        h0 = fmaf(__expf(dtc * a0), h0, dtu * Bc.x);
        h1 = fmaf(__expf(dtc * a1), h1, dtu * Bc.y);
        float y = fmaf(h0, Cc.x, h1 * Cc.y);
        y += __shfl_xor_sync(0xffffffffu, y, 1);
        y += __shfl_xor_sync(0xffffffffu, y, 2);
        y += __shfl_xor_sync(0xffffffffu, y, 4);
        if (sub == 0) {
            const float sz = zc * (1.0f / (1.0f + __expf(-zc)));
            g_ys[(t0 + l) * DI + dd] = (y + uc * Dv) * sz;
        }
    }
}

// ---------------------------------------------------------------------------
// host launcher (graph-capturable: launches only)
// ---------------------------------------------------------------------------
extern "C" void kernel_launch(void* const* d_in, const int* in_sizes, int n_in,
                              void* d_out, int out_size) {
    const float* x       = (const float*)d_in[0];
    const float* W_in    = (const float*)d_in[1];
    const float* conv_k  = (const float*)d_in[2];
    const float* conv_b  = (const float*)d_in[3];
    const float* W_xproj = (const float*)d_in[4];
    const float* W_dt    = (const float*)d_in[5];
    const float* b_dt    = (const float*)d_in[6];
    const float* A_log   = (const float*)d_in[7];
    const float* Dp      = (const float*)d_in[8];
    const float* W_out   = (const float*)d_in[9];
    float* out = (float*)d_out;

    float *xz, *u, *xdbl, *dt, *ys, *pxd, *pout;
    cudaGetSymbolAddress((void**)&xz,   g_xz);
    cudaGetSymbolAddress((void**)&u,    g_u);
    cudaGetSymbolAddress((void**)&xdbl, g_xdbl);
    cudaGetSymbolAddress((void**)&dt,   g_dt);
    cudaGetSymbolAddress((void**)&ys,   g_ys);
    cudaGetSymbolAddress((void**)&pxd,  g_pxd);
    cudaGetSymbolAddress((void**)&pout, g_pout);

    // opt-in to 75.8KB dynamic smem (attribute set is not stream work; capture-safe)
    cudaFuncSetAttribute(tgemm2<0, 0>, cudaFuncAttributeMaxDynamicSharedMemorySize, TG_SMEM_BYTES);
    cudaFuncSetAttribute(tgemm2<1, 0>, cudaFuncAttributeMaxDynamicSharedMemorySize, TG_SMEM_BYTES);
    cudaFuncSetAttribute(tgemm2<0, 1>, cudaFuncAttributeMaxDynamicSharedMemorySize, TG_SMEM_BYTES);

    // 0) A = -exp(A_log)
    prep_kernel<<<(DI * NSTATE) / 256, 256>>>(A_log);

    // 1) in_proj: xz = x @ W_in           (2048 x 4096, K=1024) — tensor tf32
    tgemm2<0, 0><<<dim3(2 * DI / 128, NT / 128, 1), 256, TG_SMEM_BYTES>>>(
        x, W_in, xz, NT, 2 * DI, DM, DM, 2 * DI, 2 * DI,
        DM, 0, nullptr);

    // 2) depthwise conv + SiLU -> u
    conv_silu_kernel<<<(NT * DI) / 256, 256>>>(conv_k, conv_b);

    // 3) xdbl = u @ W_xproj               (2048 x 160, K=2048), split-K 8 — tensor
    tgemm2<0, 1><<<dim3(2, NT / 128, 8), 256, TG_SMEM_BYTES>>>(
        u, W_xproj, pxd, NT, XPN, DI, DI, XPN, XPN,
        DI / 8, (long long)NT * XPN, nullptr);
    reduce8_kernel<<<(NT * XPN) / 256, 256>>>();

    // 4) dt = softplus(xdbl[:, :128] @ W_dt + b_dt)   (2048 x 2048, K=128) — tensor
    tgemm2<1, 0><<<dim3(DI / 128, NT / 128, 1), 256, TG_SMEM_BYTES>>>(
        xdbl, W_dt, dt, NT, DI, DTR, XPN, DI, DI,
        DTR, 0, b_dt);

    // 5) selective scan (fused skip + gate) -> ys
    scan_kernel<<<dim3(DI / 32, 2), 256>>>(Dp);

    // 6) out = ys @ W_out                 (2048 x 1024, K=2048), split-K 2 — tensor
    tgemm2<0, 0><<<dim3(DM / 128, NT / 128, 2), 256, TG_SMEM_BYTES>>>(
        ys, W_out, pout, NT, DM, DI, DI, DM, DM,
        DI / 2, (long long)NT * DM, nullptr);
    reduce2_kernel<<<(NT * DM) / 256, 256>>>(out);
}

// round 13
// speedup vs baseline: 1.0440x; 1.0440x over previous
#include <cuda_runtime.h>
#include <cuda_bf16.h>
#include <cstdint>
#include <math.h>

// ---------------------------------------------------------------------------
// Fixed problem shape:
//   BATCH=2, SEQLEN=1024, D_MODEL=1024, D_INNER=2048, DT_RANK=128, D_STATE=16,
//   D_CONV=4. Tokens NT = 2048.
// ---------------------------------------------------------------------------
#define DI      2048
#define DM      1024
#define LSEQ    1024
#define NT      2048
#define NSTATE  16
#define DTR     128
#define XPN     160      // DT_RANK + 2*D_STATE

// ----------------------- device scratch (no mallocs) -----------------------
__device__ float g_xz   [NT * 2 * DI];      // in_proj out: [x_in | z]
__device__ float g_u    [NT * DI];          // silu(conv(x_in))
__device__ float g_xdbl [NT * XPN];         // u @ W_xproj
__device__ float g_dt   [NT * DI];          // softplus(...)
__device__ float g_ys   [NT * DI];          // gated scan output
__device__ float g_A    [DI * NSTATE];      // A = -exp(A_log)
__device__ float g_pxd  [8 * NT * XPN];     // split-K partials (xproj)
__device__ float g_pout [2 * NT * DM];      // split-K partials (out)

// ----------------------- misc device helpers -------------------------------
__device__ __forceinline__ float softplus_f(float x) {
    if (x > 20.0f) return x;
    return log1pf(__expf(x));
}

// ----------------------- bf16 split/pack helpers ----------------------------
// v = hi + lo with hi,lo bf16; residual after both ~2^-18 * |v|.
// Packs element pair (e0 -> low half, e1 -> high half) matching the
// m16n8k16 fragment convention (lower 16 bits = first k element).
__device__ __forceinline__ void split_pack_bf16(float e0, float e1,
                                                unsigned& hi, unsigned& lo) {
    __nv_bfloat16 h0 = __float2bfloat16_rn(e0);
    __nv_bfloat16 h1 = __float2bfloat16_rn(e1);
    float r0 = e0 - __bfloat162float(h0);
    float r1 = e1 - __bfloat162float(h1);
    __nv_bfloat16 l0 = __float2bfloat16_rn(r0);
    __nv_bfloat16 l1 = __float2bfloat16_rn(r1);
    __nv_bfloat162 H = __halves2bfloat162(h0, h1);
    __nv_bfloat162 L = __halves2bfloat162(l0, l1);
    hi = *reinterpret_cast<unsigned*>(&H);
    lo = *reinterpret_cast<unsigned*>(&L);
}

__device__ __forceinline__ void mma_bf16(float* d, const unsigned* a, const unsigned* b) {
    asm volatile(
        "mma.sync.aligned.m16n8k16.row.col.f32.bf16.bf16.f32 "
        "{%0,%1,%2,%3}, {%4,%5,%6,%7}, {%8,%9}, {%0,%1,%2,%3};\n"
        : "+f"(d[0]), "+f"(d[1]), "+f"(d[2]), "+f"(d[3])
        : "r"(a[0]), "r"(a[1]), "r"(a[2]), "r"(a[3]), "r"(b[0]), "r"(b[1]));
}

// SMEM partition constants (32-bit words). Row stride 12 words:
// fragment loads address = 12*frow + fcol, frow 0..7 x fcol 0..3 -> all 32
// banks distinct (verified) -> conflict-free.
#define AS_W  (128 * 12)     // A tile: 128 rows x 8 kpairs (padded to 12)
#define BS_W  (128 * 12)     // B tile: 128 cols x 8 kpairs (padded to 12)
#define TG_SMEM_BYTES ((2 * AS_W * 2 + 2 * BS_W * 2) * 4)   // 49152

// ---------------------------------------------------------------------------
// Tensor-core bf16 GEMM, 3-term compensation (hi*hi + lo*hi + hi*lo),
// operands pre-split & packed bf16x2 in SMEM.
//   C[M,N] = A[M,K] @ B[K,N], row-major fp32 in/out.
//   128x128 block tile, BK=16, 256 threads = 8 warps (4x2), warp = 32x64.
//   Requires M%128==0, Kslice%16==0, N%4==0 (GUARDN=1 for N not mult of 128).
//   EPI==1 -> softplus(acc + bias[col]). blockIdx.z = split-K slice.
// ---------------------------------------------------------------------------
template <int EPI, int GUARDN>
__global__ void __launch_bounds__(256, 2)
bgemm(const float* __restrict__ A, const float* __restrict__ B,
      float* __restrict__ C, int M, int N, int K,
      int lda, int ldb, int ldc,
      int Kslice, long long cSliceStride, const float* __restrict__ bias)
{
    extern __shared__ unsigned smem_u[];
    unsigned* AsH = smem_u;                 // [2][AS_W]
    unsigned* AsL = AsH + 2 * AS_W;
    unsigned* BsH = AsL + 2 * AS_W;         // [2][BS_W]
    unsigned* BsL = BsH + 2 * BS_W;

    const int tid  = threadIdx.x;
    const int lane = tid & 31;
    const int wid  = tid >> 5;
    const int wm   = wid & 3;               // 4 warps in M
    const int wn   = wid >> 2;              // 2 warps in N
    const int bx = blockIdx.x, by = blockIdx.y, bz = blockIdx.z;

    C += (long long)bz * cSliceStride;
    const int k0 = bz * Kslice;
    const int KT = Kslice >> 4;

    // A global mapping: 128x16 tile, thread loads 8 consecutive k floats
    const int aRow = tid >> 1;
    const int aK   = (tid & 1) * 8;
    // B global mapping: 16x128 tile, thread loads 2 k-rows x 4 cols
    const int r2   = tid >> 5;              // k-pair row index 0..7
    const int cB   = (tid & 31) * 4;        // column base

    const int  gBCol = bx * 128 + cB;
    const bool bOk   = !GUARDN || (gBCol < N);   // N%4==0 -> float4 safe

    const float* Ag  = A + (long long)(by * 128 + aRow) * lda + k0 + aK;
    const float* Bg0 = B + (long long)(k0 + 2 * r2) * ldb + gBCol;

    float acc[2][8][4];
#pragma unroll
    for (int mt = 0; mt < 2; mt++)
#pragma unroll
        for (int nt = 0; nt < 8; nt++)
#pragma unroll
            for (int j = 0; j < 4; j++) acc[mt][nt][j] = 0.f;

    const int ai = aRow * 12 + (aK >> 1);   // (aK/2) in {0,4}: uint4-aligned

    // ---- preload tile 0 into buffer 0 (split+pack at store time) ----
    {
        float4 pa0 = *(const float4*)(Ag);
        float4 pa1 = *(const float4*)(Ag + 4);
        float4 q0  = bOk ? *(const float4*)(Bg0)       : make_float4(0,0,0,0);
        float4 q1  = bOk ? *(const float4*)(Bg0 + ldb) : make_float4(0,0,0,0);
        unsigned h0,h1,h2,h3, l0,l1,l2,l3;
        split_pack_bf16(pa0.x, pa0.y, h0, l0);
        split_pack_bf16(pa0.z, pa0.w, h1, l1);
        split_pack_bf16(pa1.x, pa1.y, h2, l2);
        split_pack_bf16(pa1.z, pa1.w, h3, l3);
        *(uint4*)&AsH[ai] = make_uint4(h0, h1, h2, h3);
        *(uint4*)&AsL[ai] = make_uint4(l0, l1, l2, l3);
        const float q0v[4] = {q0.x, q0.y, q0.z, q0.w};
        const float q1v[4] = {q1.x, q1.y, q1.z, q1.w};
#pragma unroll
        for (int j = 0; j < 4; j++) {
            unsigned bh, bl;
            split_pack_bf16(q0v[j], q1v[j], bh, bl);
            BsH[(cB + j) * 12 + r2] = bh;
            BsL[(cB + j) * 12 + r2] = bl;
        }
    }

    int cur = 0;
    const int frow = lane >> 2;      // 0..7
    const int fcol = lane & 3;       // 0..3

    for (int kt = 0; kt < KT; ++kt) {
        __syncthreads();

        float4 pa0, pa1, q0, q1;
        const bool more = (kt + 1 < KT);
        if (more) {
            const float* Ag2 = Ag + (kt + 1) * 16;
            const float* Bg2 = Bg0 + (long long)(kt + 1) * 16 * ldb;
            pa0 = *(const float4*)(Ag2);
            pa1 = *(const float4*)(Ag2 + 4);
            q0  = bOk ? *(const float4*)(Bg2)       : make_float4(0,0,0,0);
            q1  = bOk ? *(const float4*)(Bg2 + ldb) : make_float4(0,0,0,0);
        }

        const unsigned* ah_s = AsH + cur * AS_W;
        const unsigned* al_s = AsL + cur * AS_W;
        const unsigned* bh_s = BsH + cur * BS_W;
        const unsigned* bl_s = BsL + cur * BS_W;

        // A fragments (m16n8k16): a0=(frow,k2=fcol) a1=(+8 rows) a2=(k2+4) a3
        unsigned a_h[2][4], a_l[2][4];
#pragma unroll
        for (int mt = 0; mt < 2; mt++) {
            const int i0 = (wm * 32 + mt * 16 + frow) * 12 + fcol;
            a_h[mt][0] = ah_s[i0];       a_l[mt][0] = al_s[i0];
            a_h[mt][1] = ah_s[i0 + 96];  a_l[mt][1] = al_s[i0 + 96];   // +8 rows
            a_h[mt][2] = ah_s[i0 + 4];   a_l[mt][2] = al_s[i0 + 4];    // k+8
            a_h[mt][3] = ah_s[i0 + 100]; a_l[mt][3] = al_s[i0 + 100];
        }
#pragma unroll
        for (int nt = 0; nt < 8; nt++) {
            const int j0 = (wn * 64 + nt * 8 + frow) * 12 + fcol;
            unsigned bh[2], bl[2];
            bh[0] = bh_s[j0];     bl[0] = bl_s[j0];
            bh[1] = bh_s[j0 + 4]; bl[1] = bl_s[j0 + 4];
#pragma unroll
            for (int mt = 0; mt < 2; mt++) {
                mma_bf16(acc[mt][nt], a_h[mt], bh);   // hi*hi
                mma_bf16(acc[mt][nt], a_l[mt], bh);   // lo*hi
                mma_bf16(acc[mt][nt], a_h[mt], bl);   // hi*lo
            }
        }

        if (more) {
            const int nb = cur ^ 1;
            unsigned h0,h1,h2,h3, l0,l1,l2,l3;
            split_pack_bf16(pa0.x, pa0.y, h0, l0);
            split_pack_bf16(pa0.z, pa0.w, h1, l1);
            split_pack_bf16(pa1.x, pa1.y, h2, l2);
            split_pack_bf16(pa1.z, pa1.w, h3, l3);
            *(uint4*)&AsH[nb * AS_W + ai] = make_uint4(h0, h1, h2, h3);
            *(uint4*)&AsL[nb * AS_W + ai] = make_uint4(l0, l1, l2, l3);
            const float q0v[4] = {q0.x, q0.y, q0.z, q0.w};
            const float q1v[4] = {q1.x, q1.y, q1.z, q1.w};
#pragma unroll
            for (int j = 0; j < 4; j++) {
                unsigned bh, bl;
                split_pack_bf16(q0v[j], q1v[j], bh, bl);
                BsH[nb * BS_W + (cB + j) * 12 + r2] = bh;
                BsL[nb * BS_W + (cB + j) * 12 + r2] = bl;
            }
            cur = nb;
        }
    }

    // ---- epilogue ----
    const int rbase = by * 128 + wm * 32;
    const int cbase = bx * 128 + wn * 64;
#pragma unroll
    for (int mt = 0; mt < 2; mt++) {
#pragma unroll
        for (int nt = 0; nt < 8; nt++) {
            const int r  = rbase + mt * 16 + frow;
            const int cc = cbase + nt * 8 + fcol * 2;
            if (GUARDN && cc >= N) continue;
            float v0 = acc[mt][nt][0], v1 = acc[mt][nt][1];
            float v2 = acc[mt][nt][2], v3 = acc[mt][nt][3];
            if (EPI == 1) {
                const float b0 = bias[cc], b1 = bias[cc + 1];
                v0 = softplus_f(v0 + b0); v1 = softplus_f(v1 + b1);
                v2 = softplus_f(v2 + b0); v3 = softplus_f(v3 + b1);
            }
            *(float2*)&C[(long long)r * ldc + cc]       = make_float2(v0, v1);
            *(float2*)&C[(long long)(r + 8) * ldc + cc] = make_float2(v2, v3);
        }
    }
}

// ---------------------------------------------------------------------------
// A = -exp(A_log)
// ---------------------------------------------------------------------------
__global__ void prep_kernel(const float* __restrict__ A_log) {
    const int i = blockIdx.x * 256 + threadIdx.x;
    g_A[i] = -expf(A_log[i]);
}

// ---------------------------------------------------------------------------
// depthwise causal conv1d (kw=4) + SiLU; input = g_xz[:, :DI], out = g_u
// ---------------------------------------------------------------------------
__global__ void __launch_bounds__(256)
conv_silu_kernel(const float* __restrict__ ck, const float* __restrict__ cb) {
    const int idx = blockIdx.x * 256 + threadIdx.x;   // < NT*DI
    const int d = idx & (DI - 1);
    const int t = idx >> 11;                          // token = b*L + l
    const int l = t & (LSEQ - 1);
    float acc = cb[d];
#pragma unroll
    for (int k = 0; k < 4; k++) {
        const int ll = l + k - 3;
        if (ll >= 0)
            acc = fmaf(g_xz[(long long)(t + k - 3) * (2 * DI) + d],
                       ck[k * DI + d], acc);
    }
    g_u[idx] = acc * (1.0f / (1.0f + __expf(-acc)));
}

// ---------------------------------------------------------------------------
// split-K reductions
// ---------------------------------------------------------------------------
__global__ void reduce8_kernel() {
    const int i = blockIdx.x * 256 + threadIdx.x;     // NT*XPN
    float s = 0.f;
#pragma unroll
    for (int k = 0; k < 8; k++) s += g_pxd[(long long)k * (NT * XPN) + i];
    g_xdbl[i] = s;
}
__global__ void reduce2_kernel(float* __restrict__ out) {
    const int i = blockIdx.x * 256 + threadIdx.x;     // NT*DM
    out[i] = g_pout[i] + g_pout[NT * DM + i];
}

// ---------------------------------------------------------------------------
// selective scan: 8 threads per channel (2 states each), shfl reduce,
// one-step prefetch; fused skip (u*D) and gating (* silu(z)).
// grid: (DI/32, BATCH), block 256 -> single wave (128 blocks).
// ---------------------------------------------------------------------------
__global__ void __launch_bounds__(256)
scan_kernel(const float* __restrict__ Dp) {
    const int tid = threadIdx.x;
    const int sub = tid & 7;                          // state pair index
    const int dd  = blockIdx.x * 32 + (tid >> 3);     // channel
    const long long t0 = (long long)blockIdx.y * LSEQ;

    const float a0 = g_A[dd * NSTATE + sub * 2 + 0];
    const float a1 = g_A[dd * NSTATE + sub * 2 + 1];
    const float Dv = Dp[dd];
    float h0 = 0.f, h1 = 0.f;

    float  dt_n = g_dt[t0 * DI + dd];
    float  u_n  = g_u [t0 * DI + dd];
    float  z_n  = g_xz[t0 * (2 * DI) + DI + dd];
    float2 B_n  = *(const float2*)&g_xdbl[t0 * XPN + DTR + sub * 2];
    float2 C_n  = *(const float2*)&g_xdbl[t0 * XPN + DTR + NSTATE + sub * 2];

    for (int l = 0; l < LSEQ; ++l) {
        const float  dtc = dt_n, uc = u_n, zc = z_n;
        const float2 Bc = B_n, Cc = C_n;
        if (l + 1 < LSEQ) {
            const long long tn = t0 + l + 1;
            dt_n = g_dt[tn * DI + dd];
            u_n  = g_u [tn * DI + dd];
            z_n  = g_xz[tn * (2 * DI) + DI + dd];
            B_n  = *(const float2*)&g_xdbl[tn * XPN + DTR + sub * 2];
            C_n  = *(const float2*)&g_xdbl[tn * XPN + DTR + NSTATE + sub * 2];
        }
        const float dtu = dtc * uc;
        h0 = fmaf(__expf(dtc * a0), h0, dtu * Bc.x);
        h1 = fmaf(__expf(dtc * a1), h1, dtu * Bc.y);
        float y = fmaf(h0, Cc.x, h1 * Cc.y);
        y += __shfl_xor_sync(0xffffffffu, y, 1);
        y += __shfl_xor_sync(0xffffffffu, y, 2);
        y += __shfl_xor_sync(0xffffffffu, y, 4);
        if (sub == 0) {
            const float sz = zc * (1.0f / (1.0f + __expf(-zc)));
            g_ys[(t0 + l) * DI + dd] = (y + uc * Dv) * sz;
        }
    }
}

// ---------------------------------------------------------------------------
// host launcher (graph-capturable: launches only)
// ---------------------------------------------------------------------------
extern "C" void kernel_launch(void* const* d_in, const int* in_sizes, int n_in,
                              void* d_out, int out_size) {
    const float* x       = (const float*)d_in[0];
    const float* W_in    = (const float*)d_in[1];
    const float* conv_k  = (const float*)d_in[2];
    const float* conv_b  = (const float*)d_in[3];
    const float* W_xproj = (const float*)d_in[4];
    const float* W_dt    = (const float*)d_in[5];
    const float* b_dt    = (const float*)d_in[6];
    const float* A_log   = (const float*)d_in[7];
    const float* Dp      = (const float*)d_in[8];
    const float* W_out   = (const float*)d_in[9];
    float* out = (float*)d_out;

    float *xz, *u, *xdbl, *dt, *ys, *pxd, *pout;
    cudaGetSymbolAddress((void**)&xz,   g_xz);
    cudaGetSymbolAddress((void**)&u,    g_u);
    cudaGetSymbolAddress((void**)&xdbl, g_xdbl);
    cudaGetSymbolAddress((void**)&dt,   g_dt);
    cudaGetSymbolAddress((void**)&ys,   g_ys);
    cudaGetSymbolAddress((void**)&pxd,  g_pxd);
    cudaGetSymbolAddress((void**)&pout, g_pout);

    cudaFuncSetAttribute(bgemm<0, 0>, cudaFuncAttributeMaxDynamicSharedMemorySize, TG_SMEM_BYTES);
    cudaFuncSetAttribute(bgemm<1, 0>, cudaFuncAttributeMaxDynamicSharedMemorySize, TG_SMEM_BYTES);
    cudaFuncSetAttribute(bgemm<0, 1>, cudaFuncAttributeMaxDynamicSharedMemorySize, TG_SMEM_BYTES);

    // 0) A = -exp(A_log)
    prep_kernel<<<(DI * NSTATE) / 256, 256>>>(A_log);

    // 1) in_proj: xz = x @ W_in           (2048 x 4096, K=1024)
    bgemm<0, 0><<<dim3(2 * DI / 128, NT / 128, 1), 256, TG_SMEM_BYTES>>>(
        x, W_in, xz, NT, 2 * DI, DM, DM, 2 * DI, 2 * DI,
        DM, 0, nullptr);

    // 2) depthwise conv + SiLU -> u
    conv_silu_kernel<<<(NT * DI) / 256, 256>>>(conv_k, conv_b);

    // 3) xdbl = u @ W_xproj               (2048 x 160, K=2048), split-K 8
    bgemm<0, 1><<<dim3(2, NT / 128, 8), 256, TG_SMEM_BYTES>>>(
        u, W_xproj, pxd, NT, XPN, DI, DI, XPN, XPN,
        DI / 8, (long long)NT * XPN, nullptr);
    reduce8_kernel<<<(NT * XPN) / 256, 256>>>();

    // 4) dt = softplus(xdbl[:, :128] @ W_dt + b_dt)   (2048 x 2048, K=128)
    bgemm<1, 0><<<dim3(DI / 128, NT / 128, 1), 256, TG_SMEM_BYTES>>>(
        xdbl, W_dt, dt, NT, DI, DTR, XPN, DI, DI,
        DTR, 0, b_dt);

    // 5) selective scan (fused skip + gate) -> ys
    scan_kernel<<<dim3(DI / 32, 2), 256>>>(Dp);

    // 6) out = ys @ W_out                 (2048 x 1024, K=2048), split-K 2
    bgemm<0, 0><<<dim3(DM / 128, NT / 128, 2), 256, TG_SMEM_BYTES>>>(
        ys, W_out, pout, NT, DM, DI, DI, DM, DM,
        DI / 2, (long long)NT * DM, nullptr);
    reduce2_kernel<<<(NT * DM) / 256, 256>>>(out);
}

// round 15
// speedup vs baseline: 1.9835x; 1.9000x over previous
#include <cuda_runtime.h>
#include <cuda_bf16.h>
#include <cstdint>
#include <math.h>

// ---------------------------------------------------------------------------
// Fixed problem shape:
//   BATCH=2, SEQLEN=1024, D_MODEL=1024, D_INNER=2048, DT_RANK=128, D_STATE=16,
//   D_CONV=4. Tokens NT = 2048.
// ---------------------------------------------------------------------------
#define DI      2048
#define DM      1024
#define LSEQ    1024
#define NT      2048
#define NSTATE  16
#define DTR     128
#define XPN     160      // DT_RANK + 2*D_STATE

// ----------------------- device scratch (no mallocs) -----------------------
__device__ float g_xz   [NT * 2 * DI];      // in_proj out: [x_in | z]
__device__ float g_u    [NT * DI];          // silu(conv(x_in))
__device__ float g_xdbl [NT * XPN];         // u @ W_xproj
__device__ float g_dt   [NT * DI];          // softplus(...)
__device__ float g_ys   [NT * DI];          // gated scan output
__device__ float g_A    [DI * NSTATE];      // A = -exp(A_log)
__device__ float g_pxd  [8 * NT * XPN];     // split-K partials (xproj)
__device__ float g_pout [2 * NT * DM];      // split-K partials (out)

// pre-split bf16 hi/lo planes (packed bf16x2 along k: word i = (k=2i, k=2i+1))
__device__ uint32_t g_xh  [NT * DM / 2],      g_xl  [NT * DM / 2];        // x rows
__device__ uint32_t g_uh  [NT * DI / 2],      g_ul  [NT * DI / 2];        // u rows
__device__ uint32_t g_ysh [NT * DI / 2],      g_ysl [NT * DI / 2];        // ys rows
__device__ uint32_t g_xdh [NT * (DTR / 2)],   g_xdl [NT * (DTR / 2)];     // xdbl[:, :128]
__device__ uint32_t g_wih [(DM / 2) * 2 * DI], g_wil [(DM / 2) * 2 * DI]; // W_in  [K/2][N]
__device__ uint32_t g_wxh [(DI / 2) * XPN],    g_wxl [(DI / 2) * XPN];    // W_xproj
__device__ uint32_t g_wdh [(DTR / 2) * DI],    g_wdl [(DTR / 2) * DI];    // W_dt
__device__ uint32_t g_woh [(DI / 2) * DM],     g_wol [(DI / 2) * DM];     // W_out

// ----------------------- misc device helpers -------------------------------
__device__ __forceinline__ float softplus_f(float x) {
    if (x > 20.0f) return x;
    return log1pf(__expf(x));
}

// v = hi + lo (bf16 each); packs (e0 -> low 16, e1 -> high 16).
__device__ __forceinline__ void split_pack_bf16(float e0, float e1,
                                                uint32_t& hi, uint32_t& lo) {
    __nv_bfloat16 h0 = __float2bfloat16_rn(e0);
    __nv_bfloat16 h1 = __float2bfloat16_rn(e1);
    float r0 = e0 - __bfloat162float(h0);
    float r1 = e1 - __bfloat162float(h1);
    __nv_bfloat16 l0 = __float2bfloat16_rn(r0);
    __nv_bfloat16 l1 = __float2bfloat16_rn(r1);
    __nv_bfloat162 H = __halves2bfloat162(h0, h1);
    __nv_bfloat162 L = __halves2bfloat162(l0, l1);
    hi = *reinterpret_cast<uint32_t*>(&H);
    lo = *reinterpret_cast<uint32_t*>(&L);
}

__device__ __forceinline__ void mma_bf16(float* d, const uint32_t* a, const uint32_t* b) {
    asm volatile(
        "mma.sync.aligned.m16n8k16.row.col.f32.bf16.bf16.f32 "
        "{%0,%1,%2,%3}, {%4,%5,%6,%7}, {%8,%9}, {%0,%1,%2,%3};\n"
        : "+f"(d[0]), "+f"(d[1]), "+f"(d[2]), "+f"(d[3])
        : "r"(a[0]), "r"(a[1]), "r"(a[2]), "r"(a[3]), "r"(b[0]), "r"(b[1]));
}

// ----------------------- cp.async helpers ----------------------------------
#define CP_A16(dst, src, sz) \
    asm volatile("cp.async.cg.shared.global [%0], [%1], 16, %2;" \
                 :: "r"(dst), "l"(src), "r"(sz) : "memory")
#define CP_COMMIT() asm volatile("cp.async.commit_group;" ::: "memory")
#define CP_WAIT1()  asm volatile("cp.async.wait_group 1;" ::: "memory")

// ---------------------------------------------------------------------------
// bgemm3: tensor-core bf16 GEMM, 3-term compensation, operands pre-split in
// GLOBAL memory (hi/lo bf16x2-packed along k). cp.async 3-stage pipeline.
//   C = A[M,K] @ B[K,N] fp32 out. 128x128 CTA tile, BK=16, 8 warps (4Mx2N).
//   A planes: [M][K/2] words (row-major). B planes: [K/2][N] words.
//   Requires M%128==0, Kslice%16==0, KT>=2, N%4==0.
//   EPI==1 -> softplus(acc+bias). GUARDN -> B col guard (zfill) + store guard.
// ---------------------------------------------------------------------------
#define ST_W 5248            // stage words: AH 1536 | AL 1536 | BH 1088 | BL 1088
#define BG3_SMEM (3 * ST_W * 4)   // 62976 bytes

template <int EPI, int GUARDN>
__global__ void __launch_bounds__(256, 2)
bgemm3(const uint32_t* __restrict__ Ah, const uint32_t* __restrict__ Al, int lda2,
       const uint32_t* __restrict__ Bh, const uint32_t* __restrict__ Bl, int ldn,
       float* __restrict__ C, int N, int ldc,
       int Kslice, long long cSliceStride, const float* __restrict__ bias)
{
    extern __shared__ uint32_t smem_u[];
    const uint32_t sb = (uint32_t)__cvta_generic_to_shared(smem_u);

    const int tid  = threadIdx.x;
    const int lane = tid & 31;
    const int wid  = tid >> 5;
    const int wm   = wid & 3;
    const int wn   = wid >> 2;
    const int bx = blockIdx.x, by = blockIdx.y, bz = blockIdx.z;

    C += (long long)bz * cSliceStride;
    const int k0w = (bz * Kslice) >> 1;     // word offset along k
    const int KT  = Kslice >> 4;
    const int rb0 = by * 128, cb0 = bx * 128;

    // loader coords
    const int aRow = tid >> 1, aCh = tid & 1;            // A: 128 rows x 2 chunks
    const int bRow = tid >> 5, bCh = tid & 31;           // B: 8 kp-rows x 32 chunks
    const int gcol = cb0 + bCh * 4;
    const int bsz  = (!GUARDN || gcol < N) ? 16 : 0;     // N%4==0 -> whole chunk
    const int gcc  = bsz ? gcol : 0;

    const uint32_t* Agh = Ah + (long long)(rb0 + aRow) * lda2 + k0w + aCh * 4;
    const uint32_t* Agl = Al + (long long)(rb0 + aRow) * lda2 + k0w + aCh * 4;
    const long long bro = (long long)(k0w + bRow) * ldn + gcc;
    const uint32_t* Bgh = Bh + bro;
    const uint32_t* Bgl = Bl + bro;

    const uint32_t dA = (aRow * 12 + aCh * 4) * 4;
    const uint32_t dB = (bRow * 136 + bCh * 4) * 4;

    auto issue = [&](int kt, int st) {
        const uint32_t s0 = sb + st * (ST_W * 4);
        CP_A16(s0 + dA,                  Agh + kt * 8, 16);
        CP_A16(s0 + 1536 * 4 + dA,       Agl + kt * 8, 16);
        CP_A16(s0 + 3072 * 4 + dB,       Bgh + (long long)kt * 8 * ldn, bsz);
        CP_A16(s0 + 4160 * 4 + dB,       Bgl + (long long)kt * 8 * ldn, bsz);
    };

    float acc[2][8][4];
#pragma unroll
    for (int mt = 0; mt < 2; mt++)
#pragma unroll
        for (int nt = 0; nt < 8; nt++)
#pragma unroll
            for (int j = 0; j < 4; j++) acc[mt][nt][j] = 0.f;

    issue(0, 0); CP_COMMIT();
    issue(1, 1); CP_COMMIT();

    const int frow = lane >> 2;      // 0..7
    const int fcol = lane & 3;       // 0..3

    for (int kt = 0; kt < KT; ++kt) {
        CP_WAIT1();
        __syncthreads();

        const int st = kt % 3;
        const uint32_t* ah_s = smem_u + st * ST_W;
        const uint32_t* al_s = ah_s + 1536;
        const uint32_t* bh_s = ah_s + 3072;
        const uint32_t* bl_s = ah_s + 4160;

        uint32_t a_h[2][4], a_l[2][4];
#pragma unroll
        for (int mt = 0; mt < 2; mt++) {
            const int i0 = (wm * 32 + mt * 16 + frow) * 12 + fcol;
            a_h[mt][0] = ah_s[i0];       a_l[mt][0] = al_s[i0];
            a_h[mt][1] = ah_s[i0 + 96];  a_l[mt][1] = al_s[i0 + 96];
            a_h[mt][2] = ah_s[i0 + 4];   a_l[mt][2] = al_s[i0 + 4];
            a_h[mt][3] = ah_s[i0 + 100]; a_l[mt][3] = al_s[i0 + 100];
        }
#pragma unroll
        for (int nt = 0; nt < 8; nt++) {
            const int j0 = fcol * 136 + wn * 64 + nt * 8 + frow;
            uint32_t bh[2], bl[2];
            bh[0] = bh_s[j0];       bl[0] = bl_s[j0];
            bh[1] = bh_s[j0 + 544]; bl[1] = bl_s[j0 + 544];   // kpair+4
#pragma unroll
            for (int mt = 0; mt < 2; mt++) {
                mma_bf16(acc[mt][nt], a_h[mt], bh);   // hi*hi
                mma_bf16(acc[mt][nt], a_l[mt], bh);   // lo*hi
                mma_bf16(acc[mt][nt], a_h[mt], bl);   // hi*lo
            }
        }

        if (kt + 2 < KT) issue(kt + 2, (kt + 2) % 3);
        CP_COMMIT();                                   // keep group ledger aligned
    }

    // ---- epilogue ----
    const int rbase = rb0 + wm * 32;
    const int cbase = cb0 + wn * 64;
#pragma unroll
    for (int mt = 0; mt < 2; mt++) {
#pragma unroll
        for (int nt = 0; nt < 8; nt++) {
            const int r  = rbase + mt * 16 + frow;
            const int cc = cbase + nt * 8 + fcol * 2;
            if (GUARDN && cc >= N) continue;
            float v0 = acc[mt][nt][0], v1 = acc[mt][nt][1];
            float v2 = acc[mt][nt][2], v3 = acc[mt][nt][3];
            if (EPI == 1) {
                const float b0 = bias[cc], b1 = bias[cc + 1];
                v0 = softplus_f(v0 + b0); v1 = softplus_f(v1 + b1);
                v2 = softplus_f(v2 + b0); v3 = softplus_f(v3 + b1);
            }
            *(float2*)&C[(long long)r * ldc + cc]       = make_float2(v0, v1);
            *(float2*)&C[(long long)(r + 8) * ldc + cc] = make_float2(v2, v3);
        }
    }
}

// ---------------------------------------------------------------------------
// pack kernels: fp32 -> bf16 hi/lo planes
// ---------------------------------------------------------------------------
// A-style: in [M,K] row-major -> H/L [M][K/2] words (pair along row)
__global__ void __launch_bounds__(256)
pack_rowk(const float* __restrict__ in, uint32_t* __restrict__ H,
          uint32_t* __restrict__ L, int K2) {
    const int i = blockIdx.x * 256 + threadIdx.x;
    const float2 v = *(const float2*)&in[(long long)i * 2];
    uint32_t h, l;
    split_pack_bf16(v.x, v.y, h, l);
    H[i] = h; L[i] = l;
    (void)K2;
}
// B-style: in [K,N] row-major -> H/L [K/2][N] words (pair across rows)
__global__ void __launch_bounds__(256)
pack_colk(const float* __restrict__ in, uint32_t* __restrict__ H,
          uint32_t* __restrict__ L, int Nn) {
    const int i = blockIdx.x * 256 + threadIdx.x;
    const int n = i % Nn, kp = i / Nn;
    const float v0 = in[(long long)(2 * kp) * Nn + n];
    const float v1 = in[(long long)(2 * kp + 1) * Nn + n];
    uint32_t h, l;
    split_pack_bf16(v0, v1, h, l);
    H[i] = h; L[i] = l;
}

// ---------------------------------------------------------------------------
// A = -exp(A_log)
// ---------------------------------------------------------------------------
__global__ void prep_kernel(const float* __restrict__ A_log) {
    const int i = blockIdx.x * 256 + threadIdx.x;
    g_A[i] = -expf(A_log[i]);
}

// ---------------------------------------------------------------------------
// depthwise causal conv1d (kw=4) + SiLU; writes u fp32 AND packed hi/lo.
// one thread per channel PAIR.
// ---------------------------------------------------------------------------
__global__ void __launch_bounds__(256)
conv_silu_pack(const float* __restrict__ ck, const float* __restrict__ cb) {
    const int idx = blockIdx.x * 256 + threadIdx.x;   // < NT*DI/2
    const int d2 = idx & (DI / 2 - 1);
    const int t  = idx >> 10;
    const int l  = t & (LSEQ - 1);
    const int d0 = 2 * d2;
    float a0 = cb[d0], a1 = cb[d0 + 1];
#pragma unroll
    for (int k = 0; k < 4; k++) {
        const int ll = l + k - 3;
        if (ll >= 0) {
            const float2 xv = *(const float2*)&g_xz[(long long)(t + k - 3) * (2 * DI) + d0];
            a0 = fmaf(xv.x, ck[k * DI + d0], a0);
            a1 = fmaf(xv.y, ck[k * DI + d0 + 1], a1);
        }
    }
    const float u0 = a0 * (1.0f / (1.0f + __expf(-a0)));
    const float u1 = a1 * (1.0f / (1.0f + __expf(-a1)));
    *(float2*)&g_u[(long long)t * DI + d0] = make_float2(u0, u1);
    uint32_t h, l32;
    split_pack_bf16(u0, u1, h, l32);
    g_uh[idx] = h; g_ul[idx] = l32;
}

// ---------------------------------------------------------------------------
// split-K reductions
// ---------------------------------------------------------------------------
// xproj: 8 partials -> xdbl (fp32) + packed first 128 cols for dt-GEMM A
__global__ void __launch_bounds__(256)
reduce8_pack() {
    const int i = blockIdx.x * 256 + threadIdx.x;     // < NT*XPN/2
    const int c2 = i % (XPN / 2), t = i / (XPN / 2);
    float2 s = make_float2(0.f, 0.f);
#pragma unroll
    for (int k = 0; k < 8; k++) {
        const float2 v = *(const float2*)&g_pxd[(long long)k * (NT * XPN) + t * XPN + 2 * c2];
        s.x += v.x; s.y += v.y;
    }
    *(float2*)&g_xdbl[(long long)t * XPN + 2 * c2] = s;
    if (c2 < DTR / 2) {
        uint32_t h, l;
        split_pack_bf16(s.x, s.y, h, l);
        g_xdh[t * (DTR / 2) + c2] = h;
        g_xdl[t * (DTR / 2) + c2] = l;
    }
}
__global__ void reduce2_kernel(float* __restrict__ out) {
    const int i = blockIdx.x * 256 + threadIdx.x;     // NT*DM
    out[i] = g_pout[i] + g_pout[NT * DM + i];
}

// ---------------------------------------------------------------------------
// selective scan v2: SMEM-staged chunks (32 steps), cp.async 3-buffer pipeline.
// 8 threads per channel (2 states each), shfl reduce, fused skip+gate.
// grid (DI/32, BATCH), block 256 (32 channels). Single wave.
// ---------------------------------------------------------------------------
__global__ void __launch_bounds__(256)
scan_kernel(const float* __restrict__ Dp) {
    __shared__ float ss[3 * 4096];   // per stage: dt[1024] u[1024] z[1024] bc[1024]
    const uint32_t sb = (uint32_t)__cvta_generic_to_shared(ss);

    const int tid = threadIdx.x;
    const int sub = tid & 7;
    const int ch  = tid >> 3;                         // 0..31
    const int dd0 = blockIdx.x * 32;
    const int dd  = dd0 + ch;
    const long long t0 = (long long)blockIdx.y * LSEQ;

    const float a0 = g_A[dd * NSTATE + sub * 2 + 0];
    const float a1 = g_A[dd * NSTATE + sub * 2 + 1];
    const float Dv = Dp[dd];
    float h0 = 0.f, h1 = 0.f;

    const int ls = tid >> 3;              // loader step 0..31
    const int lc = (tid & 7) * 4;         // loader col (x4 floats)

    auto issue = [&](int chunk, int st) {
        const long long gt = t0 + chunk * 32 + ls;
        const uint32_t d = sb + (st * 4096 + ls * 32 + lc) * 4;
        CP_A16(d,            &g_dt[gt * DI + dd0 + lc], 16);
        CP_A16(d + 1024 * 4, &g_u [gt * DI + dd0 + lc], 16);
        CP_A16(d + 2048 * 4, &g_xz[gt * (2 * DI) + DI + dd0 + lc], 16);
        CP_A16(d + 3072 * 4, &g_xdbl[gt * XPN + DTR + lc], 16);
    };

    issue(0, 0); CP_COMMIT();
    issue(1, 1); CP_COMMIT();

    const int NC = LSEQ / 32;
    for (int c = 0; c < NC; ++c) {
        CP_WAIT1();
        __syncthreads();
        const float* st = ss + (c % 3) * 4096;
        const float* su = st + 1024;
        const float* sz = st + 2048;
        const float* sbc = st + 3072;
        const long long tb = t0 + c * 32;
#pragma unroll 4
        for (int s = 0; s < 32; ++s) {
            const float dtc = st[s * 32 + ch];
            const float uc  = su[s * 32 + ch];
            const float2 Bc = *(const float2*)&sbc[s * 32 + sub * 2];
            const float2 Cc = *(const float2*)&sbc[s * 32 + 16 + sub * 2];
            const float dtu = dtc * uc;
            h0 = fmaf(__expf(dtc * a0), h0, dtu * Bc.x);
            h1 = fmaf(__expf(dtc * a1), h1, dtu * Bc.y);
            float y = fmaf(h0, Cc.x, h1 * Cc.y);
            y += __shfl_xor_sync(0xffffffffu, y, 1);
            y += __shfl_xor_sync(0xffffffffu, y, 2);
            y += __shfl_xor_sync(0xffffffffu, y, 4);
            if (sub == 0) {
                const float zc = sz[s * 32 + ch];
                const float sg = zc * (1.0f / (1.0f + __expf(-zc)));
                g_ys[(tb + s) * DI + dd] = (y + uc * Dv) * sg;
            }
        }
        if (c + 2 < NC) issue(c + 2, (c + 2) % 3);
        CP_COMMIT();
    }
}

// ---------------------------------------------------------------------------
// host launcher (graph-capturable: launches only)
// ---------------------------------------------------------------------------
extern "C" void kernel_launch(void* const* d_in, const int* in_sizes, int n_in,
                              void* d_out, int out_size) {
    const float* x       = (const float*)d_in[0];
    const float* W_in    = (const float*)d_in[1];
    const float* conv_k  = (const float*)d_in[2];
    const float* conv_b  = (const float*)d_in[3];
    const float* W_xproj = (const float*)d_in[4];
    const float* W_dt    = (const float*)d_in[5];
    const float* b_dt    = (const float*)d_in[6];
    const float* A_log   = (const float*)d_in[7];
    const float* Dp      = (const float*)d_in[8];
    const float* W_out   = (const float*)d_in[9];
    float* out = (float*)d_out;

    float *xz, *xdbl, *dt, *ys, *pxd, *pout;
    cudaGetSymbolAddress((void**)&xz,   g_xz);
    cudaGetSymbolAddress((void**)&xdbl, g_xdbl);
    cudaGetSymbolAddress((void**)&dt,   g_dt);
    cudaGetSymbolAddress((void**)&ys,   g_ys);
    cudaGetSymbolAddress((void**)&pxd,  g_pxd);
    cudaGetSymbolAddress((void**)&pout, g_pout);

    uint32_t *xh,*xl,*uh,*ul,*ysh,*ysl,*xdh,*xdl;
    uint32_t *wih,*wil,*wxh,*wxl,*wdh,*wdl,*woh,*wol;
    cudaGetSymbolAddress((void**)&xh,  g_xh);  cudaGetSymbolAddress((void**)&xl,  g_xl);
    cudaGetSymbolAddress((void**)&uh,  g_uh);  cudaGetSymbolAddress((void**)&ul,  g_ul);
    cudaGetSymbolAddress((void**)&ysh, g_ysh); cudaGetSymbolAddress((void**)&ysl, g_ysl);
    cudaGetSymbolAddress((void**)&xdh, g_xdh); cudaGetSymbolAddress((void**)&xdl, g_xdl);
    cudaGetSymbolAddress((void**)&wih, g_wih); cudaGetSymbolAddress((void**)&wil, g_wil);
    cudaGetSymbolAddress((void**)&wxh, g_wxh); cudaGetSymbolAddress((void**)&wxl, g_wxl);
    cudaGetSymbolAddress((void**)&wdh, g_wdh); cudaGetSymbolAddress((void**)&wdl, g_wdl);
    cudaGetSymbolAddress((void**)&woh, g_woh); cudaGetSymbolAddress((void**)&wol, g_wol);

    cudaFuncSetAttribute(bgemm3<0, 0>, cudaFuncAttributeMaxDynamicSharedMemorySize, BG3_SMEM);
    cudaFuncSetAttribute(bgemm3<1, 0>, cudaFuncAttributeMaxDynamicSharedMemorySize, BG3_SMEM);
    cudaFuncSetAttribute(bgemm3<0, 1>, cudaFuncAttributeMaxDynamicSharedMemorySize, BG3_SMEM);

    // 0) prep: A = -exp(A_log); pack x + all weights
    prep_kernel<<<(DI * NSTATE) / 256, 256>>>(A_log);
    pack_rowk<<<(NT * DM / 2) / 256, 256>>>(x, xh, xl, DM / 2);
    pack_colk<<<((DM / 2) * 2 * DI) / 256, 256>>>(W_in, wih, wil, 2 * DI);
    pack_colk<<<((DI / 2) * XPN) / 256, 256>>>(W_xproj, wxh, wxl, XPN);
    pack_colk<<<((DTR / 2) * DI) / 256, 256>>>(W_dt, wdh, wdl, DI);
    pack_colk<<<((DI / 2) * DM) / 256, 256>>>(W_out, woh, wol, DM);

    // 1) in_proj: xz = x @ W_in           (2048 x 4096, K=1024)
    bgemm3<0, 0><<<dim3(2 * DI / 128, NT / 128, 1), 256, BG3_SMEM>>>(
        xh, xl, DM / 2, wih, wil, 2 * DI, xz, 2 * DI, 2 * DI,
        DM, 0, nullptr);

    // 2) depthwise conv + SiLU -> u (fp32 + packed)
    conv_silu_pack<<<(NT * DI / 2) / 256, 256>>>(conv_k, conv_b);

    // 3) xdbl = u @ W_xproj               (2048 x 160, K=2048), split-K 8
    bgemm3<0, 1><<<dim3(2, NT / 128, 8), 256, BG3_SMEM>>>(
        uh, ul, DI / 2, wxh, wxl, XPN, pxd, XPN, XPN,
        DI / 8, (long long)NT * XPN, nullptr);
    reduce8_pack<<<(NT * XPN / 2) / 256, 256>>>();

    // 4) dt = softplus(xdbl[:, :128] @ W_dt + b_dt)   (2048 x 2048, K=128)
    bgemm3<1, 0><<<dim3(DI / 128, NT / 128, 1), 256, BG3_SMEM>>>(
        xdh, xdl, DTR / 2, wdh, wdl, DI, dt, DI, DI,
        DTR, 0, b_dt);

    // 5) selective scan (fused skip + gate) -> ys; then pack ys
    scan_kernel<<<dim3(DI / 32, 2), 256>>>(Dp);
    pack_rowk<<<(NT * DI / 2) / 256, 256>>>(ys, ysh, ysl, DI / 2);

    // 6) out = ys @ W_out                 (2048 x 1024, K=2048), split-K 2
    bgemm3<0, 0><<<dim3(DM / 128, NT / 128, 2), 256, BG3_SMEM>>>(
        ysh, ysl, DI / 2, woh, wol, DM, pout, DM, DM,
        DI / 2, (long long)NT * DM, nullptr);
    reduce2_kernel<<<(NT * DM) / 256, 256>>>(out);
}

// round 16
// speedup vs baseline: 2.0321x; 1.0245x over previous
#include <cuda_runtime.h>
#include <cuda_bf16.h>
#include <cstdint>
#include <math.h>

// ---------------------------------------------------------------------------
// Fixed problem shape:
//   BATCH=2, SEQLEN=1024, D_MODEL=1024, D_INNER=2048, DT_RANK=128, D_STATE=16,
//   D_CONV=4. Tokens NT = 2048.
// ---------------------------------------------------------------------------
#define DI      2048
#define DM      1024
#define LSEQ    1024
#define NT      2048
#define NSTATE  16
#define DTR     128
#define XPN     160      // DT_RANK + 2*D_STATE
#define XPNP    256      // padded N for xproj B planes

// ----------------------- device scratch (no mallocs) -----------------------
__device__ float g_xz   [NT * 2 * DI];      // in_proj out: [x_in | z]
__device__ float g_u    [NT * DI];          // silu(conv(x_in))
__device__ float g_xdbl [NT * XPN];         // u @ W_xproj
__device__ float g_dt   [NT * DI];          // softplus(...)
__device__ float g_ys   [NT * DI];          // gated scan output
__device__ float g_A    [DI * NSTATE];      // A = -exp(A_log)
__device__ float g_pxd  [8 * NT * XPN];     // split-K partials (xproj)
__device__ float g_pout [2 * NT * DM];      // split-K partials (out)

// pre-split bf16 hi/lo planes in TILED fragment-native layout.
// A planes: [M/128][K/16] tiles of 1024 words; word = g*128 + lane*4 + j
//   where row=16g+frow(+8 if j&1), kpair=fcol(+4 if j>=2), lane=frow*4+fcol.
// B planes: [N/128][K/16] tiles of 1024 words; word = blk*64 + lane*2 + khi
//   where col=8*blk+frow, kpair=fcol(+4 if khi), lane=frow*4+fcol.
__device__ uint32_t g_xh  [NT * DM / 2],       g_xl  [NT * DM / 2];
__device__ uint32_t g_uh  [NT * DI / 2],       g_ul  [NT * DI / 2];
__device__ uint32_t g_ysh [NT * DI / 2],       g_ysl [NT * DI / 2];
__device__ uint32_t g_xdh [NT * (DTR / 2)],    g_xdl [NT * (DTR / 2)];
__device__ uint32_t g_wih [(DM / 2) * 2 * DI], g_wil [(DM / 2) * 2 * DI];
__device__ uint32_t g_wxh [(DI / 2) * XPNP],   g_wxl [(DI / 2) * XPNP];
__device__ uint32_t g_wdh [(DTR / 2) * DI],    g_wdl [(DTR / 2) * DI];
__device__ uint32_t g_woh [(DI / 2) * DM],     g_wol [(DI / 2) * DM];

// ----------------------- misc device helpers -------------------------------
__device__ __forceinline__ float softplus_f(float x) {
    if (x > 20.0f) return x;
    return log1pf(__expf(x));
}

__device__ __forceinline__ void split_pack_bf16(float e0, float e1,
                                                uint32_t& hi, uint32_t& lo) {
    __nv_bfloat16 h0 = __float2bfloat16_rn(e0);
    __nv_bfloat16 h1 = __float2bfloat16_rn(e1);
    float r0 = e0 - __bfloat162float(h0);
    float r1 = e1 - __bfloat162float(h1);
    __nv_bfloat16 l0 = __float2bfloat16_rn(r0);
    __nv_bfloat16 l1 = __float2bfloat16_rn(r1);
    __nv_bfloat162 H = __halves2bfloat162(h0, h1);
    __nv_bfloat162 L = __halves2bfloat162(l0, l1);
    hi = *reinterpret_cast<uint32_t*>(&H);
    lo = *reinterpret_cast<uint32_t*>(&L);
}

__device__ __forceinline__ void mma_bf16(float* d, const uint32_t* a, const uint32_t* b) {
    asm volatile(
        "mma.sync.aligned.m16n8k16.row.col.f32.bf16.bf16.f32 "
        "{%0,%1,%2,%3}, {%4,%5,%6,%7}, {%8,%9}, {%0,%1,%2,%3};\n"
        : "+f"(d[0]), "+f"(d[1]), "+f"(d[2]), "+f"(d[3])
        : "r"(a[0]), "r"(a[1]), "r"(a[2]), "r"(a[3]), "r"(b[0]), "r"(b[1]));
}

// tiled-layout index helpers (device+host logic identical)
__device__ __forceinline__ int a_tile_word(int row, int kp) {
    const int g = row >> 4;
    const int j = ((row >> 3) & 1) + 2 * (kp >> 2);
    const int lane = (row & 7) * 4 + (kp & 3);
    return g * 128 + lane * 4 + j;
}
__device__ __forceinline__ int b_tile_word(int col, int kp) {
    const int blk = col >> 3;
    const int khi = kp >> 2;
    const int lane = (col & 7) * 4 + (kp & 3);
    return blk * 64 + lane * 2 + khi;
}

// ----------------------- cp.async helpers ----------------------------------
#define CP_A16(dst, src) \
    asm volatile("cp.async.cg.shared.global [%0], [%1], 16;" \
                 :: "r"(dst), "l"(src) : "memory")
#define CP_COMMIT() asm volatile("cp.async.commit_group;" ::: "memory")
#define CP_WAIT2()  asm volatile("cp.async.wait_group 2;" ::: "memory")

// ---------------------------------------------------------------------------
// bgemm4: bf16 tensor GEMM, 3-term compensation, fragment-native tiled
// operands, 4-stage cp.async pipeline.
//   C = A[M,K] @ B[K,N] fp32. CTA tile 128x128, BK=16, 8 warps (4M x 2N).
//   A/B planes as documented above. KT = k-tiles this slice (>=4).
//   EPI==1 -> softplus(acc+bias). GUARDN -> store-guard cols >= N.
// ---------------------------------------------------------------------------
#define BG4_SMEM (4 * 4096 * 4)   // 4 stages x 16KB

template <int EPI, int GUARDN>
__global__ void __launch_bounds__(256, 2)
bgemm4(const uint32_t* __restrict__ Ah, const uint32_t* __restrict__ Al,
       const uint32_t* __restrict__ Bh, const uint32_t* __restrict__ Bl,
       float* __restrict__ C, int N, int ldc,
       int KtTot, int KT, long long cSliceStride, const float* __restrict__ bias)
{
    extern __shared__ uint32_t smem_u[];
    const uint32_t sb = (uint32_t)__cvta_generic_to_shared(smem_u);

    const int tid  = threadIdx.x;
    const int lane = tid & 31;
    const int wid  = tid >> 5;
    const int wm   = wid & 3;
    const int wn   = wid >> 2;
    const int bx = blockIdx.x, by = blockIdx.y, bz = blockIdx.z;

    C += (long long)bz * cSliceStride;
    const int kt0 = bz * KT;

    const long long aBase = (long long)(by * KtTot + kt0) * 1024 + tid * 4;
    const long long bBase = (long long)(bx * KtTot + kt0) * 1024 + tid * 4;
    const uint32_t  dSt   = sb + tid * 16;

    auto issue = [&](int kt, int st) {
        const uint32_t s0 = dSt + st * 16384;
        CP_A16(s0,             Ah + aBase + kt * 1024);
        CP_A16(s0 + 1024 * 4,  Al + aBase + kt * 1024);
        CP_A16(s0 + 2048 * 4,  Bh + bBase + kt * 1024);
        CP_A16(s0 + 3072 * 4,  Bl + bBase + kt * 1024);
    };

    float acc[2][8][4];
#pragma unroll
    for (int mt = 0; mt < 2; mt++)
#pragma unroll
        for (int nt = 0; nt < 8; nt++)
#pragma unroll
            for (int j = 0; j < 4; j++) acc[mt][nt][j] = 0.f;

    issue(0, 0); CP_COMMIT();
    issue(1, 1); CP_COMMIT();
    issue(2, 2); CP_COMMIT();

    for (int kt = 0; kt < KT; ++kt) {
        CP_WAIT2();
        __syncthreads();

        const uint32_t* s0 = smem_u + (kt & 3) * 4096;

        // A fragments: one LDS.128 per (plane, mt)
        uint32_t a_h[2][4], a_l[2][4];
#pragma unroll
        for (int mt = 0; mt < 2; mt++) {
            const int idx = (wm * 2 + mt) * 128 + lane * 4;
            const uint4 vh = *(const uint4*)(s0 + idx);
            const uint4 vl = *(const uint4*)(s0 + 1024 + idx);
            a_h[mt][0] = vh.x; a_h[mt][1] = vh.y; a_h[mt][2] = vh.z; a_h[mt][3] = vh.w;
            a_l[mt][0] = vl.x; a_l[mt][1] = vl.y; a_l[mt][2] = vl.z; a_l[mt][3] = vl.w;
        }
#pragma unroll
        for (int nt = 0; nt < 8; nt++) {
            const int bidx = 2048 + (wn * 8 + nt) * 64 + lane * 2;
            const uint2 vbh = *(const uint2*)(s0 + bidx);
            const uint2 vbl = *(const uint2*)(s0 + 1024 + bidx);
            const uint32_t bh[2] = {vbh.x, vbh.y};
            const uint32_t bl[2] = {vbl.x, vbl.y};
#pragma unroll
            for (int mt = 0; mt < 2; mt++) {
                mma_bf16(acc[mt][nt], a_h[mt], bh);   // hi*hi
                mma_bf16(acc[mt][nt], a_l[mt], bh);   // lo*hi
                mma_bf16(acc[mt][nt], a_h[mt], bl);   // hi*lo
            }
        }

        if (kt + 3 < KT) issue(kt + 3, (kt + 3) & 3);
        CP_COMMIT();
    }

    // ---- epilogue ----
    const int frow = lane >> 2, fcol = lane & 3;
    const int rbase = by * 128 + wm * 32;
    const int cbase = bx * 128 + wn * 64;
#pragma unroll
    for (int mt = 0; mt < 2; mt++) {
#pragma unroll
        for (int nt = 0; nt < 8; nt++) {
            const int r  = rbase + mt * 16 + frow;
            const int cc = cbase + nt * 8 + fcol * 2;
            if (GUARDN && cc >= N) continue;
            float v0 = acc[mt][nt][0], v1 = acc[mt][nt][1];
            float v2 = acc[mt][nt][2], v3 = acc[mt][nt][3];
            if (EPI == 1) {
                const float b0 = bias[cc], b1 = bias[cc + 1];
                v0 = softplus_f(v0 + b0); v1 = softplus_f(v1 + b1);
                v2 = softplus_f(v2 + b0); v3 = softplus_f(v3 + b1);
            }
            *(float2*)&C[(long long)r * ldc + cc]       = make_float2(v0, v1);
            *(float2*)&C[(long long)(r + 8) * ldc + cc] = make_float2(v2, v3);
        }
    }
}

// ---------------------------------------------------------------------------
// pack kernels (fp32 -> tiled hi/lo planes)
// ---------------------------------------------------------------------------
// A-style: in [M,K] row-major. KtTot = K/16.
__global__ void __launch_bounds__(256)
pack_a_tiled(const float* __restrict__ in, uint32_t* __restrict__ H,
             uint32_t* __restrict__ L, int K) {
    const int i = blockIdx.x * 256 + threadIdx.x;     // over M*K/2
    const int K2 = K >> 1;
    const int kpg = i % K2, rowg = i / K2;
    const int mt = rowg >> 7, row = rowg & 127;
    const int kt = kpg >> 3,  kp  = kpg & 7;
    const long long off = (long long)(mt * (K >> 4) + kt) * 1024 + a_tile_word(row, kp);
    const float2 v = *(const float2*)&in[(long long)rowg * K + 2 * kpg];
    uint32_t h, l;
    split_pack_bf16(v.x, v.y, h, l);
    H[off] = h; L[off] = l;
}
// B-style: in [K,N] row-major, planes padded to Npad cols. KtTot = K/16.
__global__ void __launch_bounds__(256)
pack_b_tiled(const float* __restrict__ in, uint32_t* __restrict__ H,
             uint32_t* __restrict__ L, int K, int N, int Npad) {
    const int i = blockIdx.x * 256 + threadIdx.x;     // over (K/2)*Npad
    const int n = i % Npad, kpg = i / Npad;
    const int kt = kpg >> 3, kp = kpg & 7;
    const int nt = n >> 7,   col = n & 127;
    const long long off = (long long)(nt * (K >> 4) + kt) * 1024 + b_tile_word(col, kp);
    float v0 = 0.f, v1 = 0.f;
    if (n < N) {
        v0 = in[(long long)(2 * kpg) * N + n];
        v1 = in[(long long)(2 * kpg + 1) * N + n];
    }
    uint32_t h, l;
    split_pack_bf16(v0, v1, h, l);
    H[off] = h; L[off] = l;
}

// ---------------------------------------------------------------------------
// A = -exp(A_log)
// ---------------------------------------------------------------------------
__global__ void prep_kernel(const float* __restrict__ A_log) {
    const int i = blockIdx.x * 256 + threadIdx.x;
    g_A[i] = -expf(A_log[i]);
}

// ---------------------------------------------------------------------------
// depthwise causal conv1d (kw=4) + SiLU; writes u fp32 AND tiled hi/lo planes.
// one thread per channel PAIR.
// ---------------------------------------------------------------------------
__global__ void __launch_bounds__(256)
conv_silu_pack(const float* __restrict__ ck, const float* __restrict__ cb) {
    const int idx = blockIdx.x * 256 + threadIdx.x;   // < NT*DI/2
    const int d2 = idx & (DI / 2 - 1);
    const int t  = idx >> 10;
    const int l  = t & (LSEQ - 1);
    const int d0 = 2 * d2;
    float a0 = cb[d0], a1 = cb[d0 + 1];
#pragma unroll
    for (int k = 0; k < 4; k++) {
        const int ll = l + k - 3;
        if (ll >= 0) {
            const float2 xv = *(const float2*)&g_xz[(long long)(t + k - 3) * (2 * DI) + d0];
            a0 = fmaf(xv.x, ck[k * DI + d0], a0);
            a1 = fmaf(xv.y, ck[k * DI + d0 + 1], a1);
        }
    }
    const float u0 = a0 * (1.0f / (1.0f + __expf(-a0)));
    const float u1 = a1 * (1.0f / (1.0f + __expf(-a1)));
    *(float2*)&g_u[(long long)t * DI + d0] = make_float2(u0, u1);
    uint32_t h, l32;
    split_pack_bf16(u0, u1, h, l32);
    const int mt = t >> 7, row = t & 127, kt = d2 >> 3, kp = d2 & 7;
    const long long off = (long long)(mt * (DI >> 4) + kt) * 1024 + a_tile_word(row, kp);
    g_uh[off] = h; g_ul[off] = l32;
}

// ---------------------------------------------------------------------------
// split-K reductions
// ---------------------------------------------------------------------------
// xproj: 8 partials -> xdbl fp32 + tiled pack of first 128 cols (dt-GEMM A)
__global__ void __launch_bounds__(256)
reduce8_pack() {
    const int i = blockIdx.x * 256 + threadIdx.x;     // < NT*XPN/2
    const int c2 = i % (XPN / 2), t = i / (XPN / 2);
    float2 s = make_float2(0.f, 0.f);
#pragma unroll
    for (int k = 0; k < 8; k++) {
        const float2 v = *(const float2*)&g_pxd[(long long)k * (NT * XPN) + t * XPN + 2 * c2];
        s.x += v.x; s.y += v.y;
    }
    *(float2*)&g_xdbl[(long long)t * XPN + 2 * c2] = s;
    if (c2 < DTR / 2) {
        uint32_t h, l;
        split_pack_bf16(s.x, s.y, h, l);
        const int mt = t >> 7, row = t & 127, kt = c2 >> 3, kp = c2 & 7;
        const long long off = (long long)(mt * (DTR >> 4) + kt) * 1024 + a_tile_word(row, kp);
        g_xdh[off] = h; g_xdl[off] = l;
    }
}
__global__ void reduce2_kernel(float* __restrict__ out) {
    const int i = blockIdx.x * 256 + threadIdx.x;     // NT*DM
    out[i] = g_pout[i] + g_pout[NT * DM + i];
}

// ---------------------------------------------------------------------------
// selective scan: SMEM-staged chunks (32 steps), cp.async 3-buffer pipeline.
// 8 threads per channel (2 states each), shfl reduce, fused skip+gate.
// grid (DI/32, BATCH), block 256. Single wave.
// ---------------------------------------------------------------------------
#define SCP_A16(dst, src) \
    asm volatile("cp.async.cg.shared.global [%0], [%1], 16;" \
                 :: "r"(dst), "l"(src) : "memory")
__global__ void __launch_bounds__(256)
scan_kernel(const float* __restrict__ Dp) {
    __shared__ float ss[3 * 4096];
    const uint32_t sb = (uint32_t)__cvta_generic_to_shared(ss);

    const int tid = threadIdx.x;
    const int sub = tid & 7;
    const int ch  = tid >> 3;
    const int dd0 = blockIdx.x * 32;
    const int dd  = dd0 + ch;
    const long long t0 = (long long)blockIdx.y * LSEQ;

    const float a0 = g_A[dd * NSTATE + sub * 2 + 0];
    const float a1 = g_A[dd * NSTATE + sub * 2 + 1];
    const float Dv = Dp[dd];
    float h0 = 0.f, h1 = 0.f;

    const int ls = tid >> 3;
    const int lc = (tid & 7) * 4;

    auto issue = [&](int chunk, int st) {
        const long long gt = t0 + chunk * 32 + ls;
        const uint32_t d = sb + (st * 4096 + ls * 32 + lc) * 4;
        SCP_A16(d,            &g_dt[gt * DI + dd0 + lc]);
        SCP_A16(d + 1024 * 4, &g_u [gt * DI + dd0 + lc]);
        SCP_A16(d + 2048 * 4, &g_xz[gt * (2 * DI) + DI + dd0 + lc]);
        SCP_A16(d + 3072 * 4, &g_xdbl[gt * XPN + DTR + lc]);
    };

    issue(0, 0); CP_COMMIT();
    issue(1, 1); CP_COMMIT();

    const int NC = LSEQ / 32;
    for (int c = 0; c < NC; ++c) {
        asm volatile("cp.async.wait_group 1;" ::: "memory");
        __syncthreads();
        const float* st = ss + (c % 3) * 4096;
        const float* su = st + 1024;
        const float* sz = st + 2048;
        const float* sbc = st + 3072;
        const long long tb = t0 + c * 32;
#pragma unroll 4
        for (int s = 0; s < 32; ++s) {
            const float dtc = st[s * 32 + ch];
            const float uc  = su[s * 32 + ch];
            const float2 Bc = *(const float2*)&sbc[s * 32 + sub * 2];
            const float2 Cc = *(const float2*)&sbc[s * 32 + 16 + sub * 2];
            const float dtu = dtc * uc;
            h0 = fmaf(__expf(dtc * a0), h0, dtu * Bc.x);
            h1 = fmaf(__expf(dtc * a1), h1, dtu * Bc.y);
            float y = fmaf(h0, Cc.x, h1 * Cc.y);
            y += __shfl_xor_sync(0xffffffffu, y, 1);
            y += __shfl_xor_sync(0xffffffffu, y, 2);
            y += __shfl_xor_sync(0xffffffffu, y, 4);
            if (sub == 0) {
                const float zc = sz[s * 32 + ch];
                const float sg = zc * (1.0f / (1.0f + __expf(-zc)));
                g_ys[(tb + s) * DI + dd] = (y + uc * Dv) * sg;
            }
        }
        if (c + 2 < NC) issue(c + 2, (c + 2) % 3);
        CP_COMMIT();
    }
}

// ---------------------------------------------------------------------------
// host launcher (graph-capturable: launches only)
// ---------------------------------------------------------------------------
extern "C" void kernel_launch(void* const* d_in, const int* in_sizes, int n_in,
                              void* d_out, int out_size) {
    const float* x       = (const float*)d_in[0];
    const float* W_in    = (const float*)d_in[1];
    const float* conv_k  = (const float*)d_in[2];
    const float* conv_b  = (const float*)d_in[3];
    const float* W_xproj = (const float*)d_in[4];
    const float* W_dt    = (const float*)d_in[5];
    const float* b_dt    = (const float*)d_in[6];
    const float* A_log   = (const float*)d_in[7];
    const float* Dp      = (const float*)d_in[8];
    const float* W_out   = (const float*)d_in[9];
    float* out = (float*)d_out;

    float *xz, *dt, *ys, *pxd, *pout;
    cudaGetSymbolAddress((void**)&xz,   g_xz);
    cudaGetSymbolAddress((void**)&dt,   g_dt);
    cudaGetSymbolAddress((void**)&ys,   g_ys);
    cudaGetSymbolAddress((void**)&pxd,  g_pxd);
    cudaGetSymbolAddress((void**)&pout, g_pout);

    uint32_t *xh,*xl,*uh,*ul,*ysh,*ysl,*xdh,*xdl;
    uint32_t *wih,*wil,*wxh,*wxl,*wdh,*wdl,*woh,*wol;
    cudaGetSymbolAddress((void**)&xh,  g_xh);  cudaGetSymbolAddress((void**)&xl,  g_xl);
    cudaGetSymbolAddress((void**)&uh,  g_uh);  cudaGetSymbolAddress((void**)&ul,  g_ul);
    cudaGetSymbolAddress((void**)&ysh, g_ysh); cudaGetSymbolAddress((void**)&ysl, g_ysl);
    cudaGetSymbolAddress((void**)&xdh, g_xdh); cudaGetSymbolAddress((void**)&xdl, g_xdl);
    cudaGetSymbolAddress((void**)&wih, g_wih); cudaGetSymbolAddress((void**)&wil, g_wil);
    cudaGetSymbolAddress((void**)&wxh, g_wxh); cudaGetSymbolAddress((void**)&wxl, g_wxl);
    cudaGetSymbolAddress((void**)&wdh, g_wdh); cudaGetSymbolAddress((void**)&wdl, g_wdl);
    cudaGetSymbolAddress((void**)&woh, g_woh); cudaGetSymbolAddress((void**)&wol, g_wol);

    cudaFuncSetAttribute(bgemm4<0, 0>, cudaFuncAttributeMaxDynamicSharedMemorySize, BG4_SMEM);
    cudaFuncSetAttribute(bgemm4<1, 0>, cudaFuncAttributeMaxDynamicSharedMemorySize, BG4_SMEM);
    cudaFuncSetAttribute(bgemm4<0, 1>, cudaFuncAttributeMaxDynamicSharedMemorySize, BG4_SMEM);

    // 0) prep + packs
    prep_kernel<<<(DI * NSTATE) / 256, 256>>>(A_log);
    pack_a_tiled<<<(NT * DM / 2) / 256, 256>>>(x, xh, xl, DM);
    pack_b_tiled<<<((DM / 2) * 2 * DI) / 256, 256>>>(W_in, wih, wil, DM, 2 * DI, 2 * DI);
    pack_b_tiled<<<((DI / 2) * XPNP) / 256, 256>>>(W_xproj, wxh, wxl, DI, XPN, XPNP);
    pack_b_tiled<<<((DTR / 2) * DI) / 256, 256>>>(W_dt, wdh, wdl, DTR, DI, DI);
    pack_b_tiled<<<((DI / 2) * DM) / 256, 256>>>(W_out, woh, wol, DI, DM, DM);

    // 1) in_proj: xz = x @ W_in           (2048 x 4096, K=1024)
    bgemm4<0, 0><<<dim3(2 * DI / 128, NT / 128, 1), 256, BG4_SMEM>>>(
        xh, xl, wih, wil, xz, 2 * DI, 2 * DI,
        DM / 16, DM / 16, 0, nullptr);

    // 2) depthwise conv + SiLU -> u (fp32 + tiled planes)
    conv_silu_pack<<<(NT * DI / 2) / 256, 256>>>(conv_k, conv_b);

    // 3) xdbl = u @ W_xproj               (2048 x 160, K=2048), split-K 8
    bgemm4<0, 1><<<dim3(2, NT / 128, 8), 256, BG4_SMEM>>>(
        uh, ul, wxh, wxl, pxd, XPN, XPN,
        DI / 16, (DI / 8) / 16, (long long)NT * XPN, nullptr);
    reduce8_pack<<<(NT * XPN / 2) / 256, 256>>>();

    // 4) dt = softplus(xdbl[:, :128] @ W_dt + b_dt)   (2048 x 2048, K=128)
    bgemm4<1, 0><<<dim3(DI / 128, NT / 128, 1), 256, BG4_SMEM>>>(
        xdh, xdl, wdh, wdl, dt, DI, DI,
        DTR / 16, DTR / 16, 0, b_dt);

    // 5) selective scan (fused skip + gate) -> ys; then pack ys
    scan_kernel<<<dim3(DI / 32, 2), 256>>>(Dp);
    pack_a_tiled<<<(NT * DI / 2) / 256, 256>>>(ys, ysh, ysl, DI);

    // 6) out = ys @ W_out                 (2048 x 1024, K=2048), split-K 2
    bgemm4<0, 0><<<dim3(DM / 128, NT / 128, 2), 256, BG4_SMEM>>>(
        ysh, ysl, woh, wol, pout, DM, DM,
        DI / 16, (DI / 2) / 16, (long long)NT * DM, nullptr);
    reduce2_kernel<<<(NT * DM) / 256, 256>>>(out);
}

// round 17
// speedup vs baseline: 2.5301x; 1.2451x over previous
#include <cuda_runtime.h>
#include <cuda_fp16.h>
#include <cstdint>
#include <math.h>

// ---------------------------------------------------------------------------
// Fixed problem shape:
//   BATCH=2, SEQLEN=1024, D_MODEL=1024, D_INNER=2048, DT_RANK=128, D_STATE=16,
//   D_CONV=4. Tokens NT = 2048.
// ---------------------------------------------------------------------------
#define DI      2048
#define DM      1024
#define LSEQ    1024
#define NT      2048
#define NSTATE  16
#define DTR     128
#define XPN     160      // DT_RANK + 2*D_STATE
#define XPNP    256      // padded N for xproj B planes

// ----------------------- device scratch (no mallocs) -----------------------
__device__ float g_xz   [NT * 2 * DI];      // in_proj out: [x_in | z]
__device__ float g_u    [NT * DI];          // silu(conv(x_in))
__device__ float g_xdbl [NT * XPN];         // u @ W_xproj
__device__ float g_dt   [NT * DI];          // softplus(...)
__device__ float g_A    [DI * NSTATE];      // A = -exp(A_log)
__device__ float g_pxd  [8 * NT * XPN];     // split-K partials (xproj)
__device__ float g_pout [2 * NT * DM];      // split-K partials (out)

// fp16 planes, fragment-native tiled layout.
// A planes (hi+lo): [M/128][K/16] tiles of 1024 words; see a_tile_word.
// B planes (hi only): [N/128][K/16] tiles of 1024 words; see b_tile_word
//   (nt-pair interleaved so one LDS.128 covers two 8-col blocks).
__device__ uint32_t g_xh  [NT * DM / 2],       g_xl  [NT * DM / 2];
__device__ uint32_t g_uh  [NT * DI / 2],       g_ul  [NT * DI / 2];
__device__ uint32_t g_ysh [NT * DI / 2],       g_ysl [NT * DI / 2];
__device__ uint32_t g_xdh [NT * (DTR / 2)],    g_xdl [NT * (DTR / 2)];
__device__ uint32_t g_wih [(DM / 2) * 2 * DI];
__device__ uint32_t g_wxh [(DI / 2) * XPNP];
__device__ uint32_t g_wdh [(DTR / 2) * DI];
__device__ uint32_t g_woh [(DI / 2) * DM];

// ----------------------- misc device helpers -------------------------------
__device__ __forceinline__ float softplus_f(float x) {
    if (x > 20.0f) return x;
    return log1pf(__expf(x));
}

// a = hi + lo (fp16 each); packs (e0 -> low 16, e1 -> high 16).
__device__ __forceinline__ void split_pack_f16(float e0, float e1,
                                               uint32_t& hi, uint32_t& lo) {
    __half h0 = __float2half_rn(e0);
    __half h1 = __float2half_rn(e1);
    float r0 = e0 - __half2float(h0);
    float r1 = e1 - __half2float(h1);
    __half l0 = __float2half_rn(r0);
    __half l1 = __float2half_rn(r1);
    __half2 H = __halves2half2(h0, h1);
    __half2 L = __halves2half2(l0, l1);
    hi = *reinterpret_cast<uint32_t*>(&H);
    lo = *reinterpret_cast<uint32_t*>(&L);
}
__device__ __forceinline__ uint32_t pack_f16(float e0, float e1) {
    __half2 H = __halves2half2(__float2half_rn(e0), __float2half_rn(e1));
    return *reinterpret_cast<uint32_t*>(&H);
}

__device__ __forceinline__ void mma_f16(float* d, const uint32_t* a, const uint32_t* b) {
    asm volatile(
        "mma.sync.aligned.m16n8k16.row.col.f32.f16.f16.f32 "
        "{%0,%1,%2,%3}, {%4,%5,%6,%7}, {%8,%9}, {%0,%1,%2,%3};\n"
        : "+f"(d[0]), "+f"(d[1]), "+f"(d[2]), "+f"(d[3])
        : "r"(a[0]), "r"(a[1]), "r"(a[2]), "r"(a[3]), "r"(b[0]), "r"(b[1]));
}

// tiled-layout index helpers
__device__ __forceinline__ int a_tile_word(int row, int kp) {
    const int g = row >> 4;
    const int j = ((row >> 3) & 1) + 2 * (kp >> 2);
    const int lane = (row & 7) * 4 + (kp & 3);
    return g * 128 + lane * 4 + j;
}
// nt-pair interleaved B word: LDS.128 at (blkpair*128 + lane*4) yields
// {even-blk khi0, even khi1, odd khi0, odd khi1}.
__device__ __forceinline__ int b_tile_word(int col, int kp) {
    const int blk = col >> 3;
    const int khi = kp >> 2;
    const int lane = (col & 7) * 4 + (kp & 3);
    return (blk >> 1) * 128 + lane * 4 + (blk & 1) * 2 + khi;
}

// ----------------------- cp.async helpers ----------------------------------
#define CP_A16(dst, src) \
    asm volatile("cp.async.cg.shared.global [%0], [%1], 16;" \
                 :: "r"(dst), "l"(src) : "memory")
#define CP_COMMIT() asm volatile("cp.async.commit_group;" ::: "memory")

// ---------------------------------------------------------------------------
// bgemm5: fp16 tensor GEMM, 2-term compensation (split A, rounded B),
// fragment-native tiled operands, 4-stage cp.async pipeline.
//   C = A[M,K] @ B[K,N] fp32. CTA 128x128, BK=16, 8 warps (4M x 2N).
//   Stage = AH 1024w | AL 1024w | BH 1024w = 12KB.
// ---------------------------------------------------------------------------
#define BG5_SMEM (4 * 3072 * 4)   // 49152

template <int EPI, int GUARDN>
__global__ void __launch_bounds__(256, 2)
bgemm5(const uint32_t* __restrict__ Ah, const uint32_t* __restrict__ Al,
       const uint32_t* __restrict__ Bh,
       float* __restrict__ C, int N, int ldc,
       int KtTot, int KT, long long cSliceStride, const float* __restrict__ bias)
{
    extern __shared__ uint32_t smem_u[];
    const uint32_t sb = (uint32_t)__cvta_generic_to_shared(smem_u);

    const int tid  = threadIdx.x;
    const int lane = tid & 31;
    const int wid  = tid >> 5;
    const int wm   = wid & 3;
    const int wn   = wid >> 2;
    const int bx = blockIdx.x, by = blockIdx.y, bz = blockIdx.z;

    C += (long long)bz * cSliceStride;
    const int kt0 = bz * KT;

    const long long aBase = (long long)(by * KtTot + kt0) * 1024 + tid * 4;
    const long long bBase = (long long)(bx * KtTot + kt0) * 1024 + tid * 4;
    const uint32_t  dSt   = sb + tid * 16;

    auto issue = [&](int kt, int st) {
        const uint32_t s0 = dSt + st * 12288;
        CP_A16(s0,            Ah + aBase + kt * 1024);
        CP_A16(s0 + 1024 * 4, Al + aBase + kt * 1024);
        CP_A16(s0 + 2048 * 4, Bh + bBase + kt * 1024);
    };

    float acc[2][8][4];
#pragma unroll
    for (int mt = 0; mt < 2; mt++)
#pragma unroll
        for (int nt = 0; nt < 8; nt++)
#pragma unroll
            for (int j = 0; j < 4; j++) acc[mt][nt][j] = 0.f;

    issue(0, 0); CP_COMMIT();
    issue(1, 1); CP_COMMIT();
    issue(2, 2); CP_COMMIT();

    for (int kt = 0; kt < KT; ++kt) {
        asm volatile("cp.async.wait_group 2;" ::: "memory");
        __syncthreads();

        const uint32_t* s0 = smem_u + (kt & 3) * 3072;

        uint32_t a_h[2][4], a_l[2][4];
#pragma unroll
        for (int mt = 0; mt < 2; mt++) {
            const int idx = (wm * 2 + mt) * 128 + lane * 4;
            const uint4 vh = *(const uint4*)(s0 + idx);
            const uint4 vl = *(const uint4*)(s0 + 1024 + idx);
            a_h[mt][0] = vh.x; a_h[mt][1] = vh.y; a_h[mt][2] = vh.z; a_h[mt][3] = vh.w;
            a_l[mt][0] = vl.x; a_l[mt][1] = vl.y; a_l[mt][2] = vl.z; a_l[mt][3] = vl.w;
        }
#pragma unroll
        for (int ntp = 0; ntp < 4; ntp++) {
            const int bidx = 2048 + (wn * 4 + ntp) * 128 + lane * 4;
            const uint4 vb = *(const uint4*)(s0 + bidx);
            const uint32_t bE[2] = {vb.x, vb.y};
            const uint32_t bO[2] = {vb.z, vb.w};
#pragma unroll
            for (int mt = 0; mt < 2; mt++) {
                mma_f16(acc[mt][2 * ntp],     a_h[mt], bE);
                mma_f16(acc[mt][2 * ntp],     a_l[mt], bE);
                mma_f16(acc[mt][2 * ntp + 1], a_h[mt], bO);
                mma_f16(acc[mt][2 * ntp + 1], a_l[mt], bO);
            }
        }

        if (kt + 3 < KT) issue(kt + 3, (kt + 3) & 3);
        CP_COMMIT();
    }

    // ---- epilogue ----
    const int frow = lane >> 2, fcol = lane & 3;
    const int rbase = by * 128 + wm * 32;
    const int cbase = bx * 128 + wn * 64;
#pragma unroll
    for (int mt = 0; mt < 2; mt++) {
#pragma unroll
        for (int nt = 0; nt < 8; nt++) {
            const int r  = rbase + mt * 16 + frow;
            const int cc = cbase + nt * 8 + fcol * 2;
            if (GUARDN && cc >= N) continue;
            float v0 = acc[mt][nt][0], v1 = acc[mt][nt][1];
            float v2 = acc[mt][nt][2], v3 = acc[mt][nt][3];
            if (EPI == 1) {
                const float b0 = bias[cc], b1 = bias[cc + 1];
                v0 = softplus_f(v0 + b0); v1 = softplus_f(v1 + b1);
                v2 = softplus_f(v2 + b0); v3 = softplus_f(v3 + b1);
            }
            *(float2*)&C[(long long)r * ldc + cc]       = make_float2(v0, v1);
            *(float2*)&C[(long long)(r + 8) * ldc + cc] = make_float2(v2, v3);
        }
    }
}

// ---------------------------------------------------------------------------
// pack kernels
// ---------------------------------------------------------------------------
// A-style: [M,K] row-major -> tiled hi/lo fp16 planes.
__global__ void __launch_bounds__(256)
pack_a_tiled(const float* __restrict__ in, uint32_t* __restrict__ H,
             uint32_t* __restrict__ L, int K) {
    const int i = blockIdx.x * 256 + threadIdx.x;     // over M*K/2
    const int K2 = K >> 1;
    const int kpg = i % K2, rowg = i / K2;
    const int mt = rowg >> 7, row = rowg & 127;
    const int kt = kpg >> 3,  kp  = kpg & 7;
    const long long off = (long long)(mt * (K >> 4) + kt) * 1024 + a_tile_word(row, kp);
    const float2 v = *(const float2*)&in[(long long)rowg * K + 2 * kpg];
    uint32_t h, l;
    split_pack_f16(v.x, v.y, h, l);
    H[off] = h; L[off] = l;
}
// B-style: [K,N] row-major -> tiled hi-only fp16 plane (padded to Npad cols).
__global__ void __launch_bounds__(256)
pack_b_tiled(const float* __restrict__ in, uint32_t* __restrict__ H,
             int K, int N, int Npad) {
    const int i = blockIdx.x * 256 + threadIdx.x;     // over (K/2)*Npad
    const int n = i % Npad, kpg = i / Npad;
    const int kt = kpg >> 3, kp = kpg & 7;
    const int nt = n >> 7,   col = n & 127;
    const long long off = (long long)(nt * (K >> 4) + kt) * 1024 + b_tile_word(col, kp);
    float v0 = 0.f, v1 = 0.f;
    if (n < N) {
        v0 = in[(long long)(2 * kpg) * N + n];
        v1 = in[(long long)(2 * kpg + 1) * N + n];
    }
    H[off] = pack_f16(v0, v1);
}

// ---------------------------------------------------------------------------
// A = -exp(A_log)
// ---------------------------------------------------------------------------
__global__ void prep_kernel(const float* __restrict__ A_log) {
    const int i = blockIdx.x * 256 + threadIdx.x;
    g_A[i] = -expf(A_log[i]);
}

// ---------------------------------------------------------------------------
// depthwise causal conv1d (kw=4) + SiLU -> u fp32 + tiled fp16 planes.
// ---------------------------------------------------------------------------
__global__ void __launch_bounds__(256)
conv_silu_pack(const float* __restrict__ ck, const float* __restrict__ cb) {
    const int idx = blockIdx.x * 256 + threadIdx.x;   // < NT*DI/2
    const int d2 = idx & (DI / 2 - 1);
    const int t  = idx >> 10;
    const int l  = t & (LSEQ - 1);
    const int d0 = 2 * d2;
    float a0 = cb[d0], a1 = cb[d0 + 1];
#pragma unroll
    for (int k = 0; k < 4; k++) {
        const int ll = l + k - 3;
        if (ll >= 0) {
            const float2 xv = *(const float2*)&g_xz[(long long)(t + k - 3) * (2 * DI) + d0];
            a0 = fmaf(xv.x, ck[k * DI + d0], a0);
            a1 = fmaf(xv.y, ck[k * DI + d0 + 1], a1);
        }
    }
    const float u0 = a0 * (1.0f / (1.0f + __expf(-a0)));
    const float u1 = a1 * (1.0f / (1.0f + __expf(-a1)));
    *(float2*)&g_u[(long long)t * DI + d0] = make_float2(u0, u1);
    uint32_t h, l32;
    split_pack_f16(u0, u1, h, l32);
    const int mt = t >> 7, row = t & 127, kt = d2 >> 3, kp = d2 & 7;
    const long long off = (long long)(mt * (DI >> 4) + kt) * 1024 + a_tile_word(row, kp);
    g_uh[off] = h; g_ul[off] = l32;
}

// ---------------------------------------------------------------------------
// split-K reductions
// ---------------------------------------------------------------------------
__global__ void __launch_bounds__(256)
reduce8_pack() {
    const int i = blockIdx.x * 256 + threadIdx.x;     // < NT*XPN/2
    const int c2 = i % (XPN / 2), t = i / (XPN / 2);
    float2 s = make_float2(0.f, 0.f);
#pragma unroll
    for (int k = 0; k < 8; k++) {
        const float2 v = *(const float2*)&g_pxd[(long long)k * (NT * XPN) + t * XPN + 2 * c2];
        s.x += v.x; s.y += v.y;
    }
    *(float2*)&g_xdbl[(long long)t * XPN + 2 * c2] = s;
    if (c2 < DTR / 2) {
        uint32_t h, l;
        split_pack_f16(s.x, s.y, h, l);
        const int mt = t >> 7, row = t & 127, kt = c2 >> 3, kp = c2 & 7;
        const long long off = (long long)(mt * (DTR >> 4) + kt) * 1024 + a_tile_word(row, kp);
        g_xdh[off] = h; g_xdl[off] = l;
    }
}
__global__ void reduce2_kernel(float* __restrict__ out) {
    const int i = blockIdx.x * 256 + threadIdx.x;     // NT*DM
    out[i] = g_pout[i] + g_pout[NT * DM + i];
}

// ---------------------------------------------------------------------------
// selective scan: SMEM-staged 32-step chunks (cp.async, 3 buffers), fused
// skip+gate, and FUSED ys fp16 hi/lo plane packing (no fp32 ys round-trip).
// grid (DI/32, BATCH), block 256. Dynamic smem 52KB.
// ---------------------------------------------------------------------------
#define SCAN_SMEM ((3 * 4096 + 1024) * 4)
__global__ void __launch_bounds__(256)
scan_kernel(const float* __restrict__ Dp) {
    extern __shared__ float ss[];                      // 3*4096 stage + 1024 ybuf
    float* ybuf = ss + 3 * 4096;
    const uint32_t sb = (uint32_t)__cvta_generic_to_shared(ss);

    const int tid = threadIdx.x;
    const int sub = tid & 7;
    const int ch  = tid >> 3;
    const int dd0 = blockIdx.x * 32;
    const int dd  = dd0 + ch;
    const long long t0 = (long long)blockIdx.y * LSEQ;

    const float a0 = g_A[dd * NSTATE + sub * 2 + 0];
    const float a1 = g_A[dd * NSTATE + sub * 2 + 1];
    const float Dv = Dp[dd];
    float h0 = 0.f, h1 = 0.f;

    const int ls = tid >> 3;
    const int lc = (tid & 7) * 4;

    auto issue = [&](int chunk, int st) {
        const long long gt = t0 + chunk * 32 + ls;
        const uint32_t d = sb + (st * 4096 + ls * 32 + lc) * 4;
        CP_A16(d,            &g_dt[gt * DI + dd0 + lc]);
        CP_A16(d + 1024 * 4, &g_u [gt * DI + dd0 + lc]);
        CP_A16(d + 2048 * 4, &g_xz[gt * (2 * DI) + DI + dd0 + lc]);
        CP_A16(d + 3072 * 4, &g_xdbl[gt * XPN + DTR + lc]);
    };

    issue(0, 0); CP_COMMIT();
    issue(1, 1); CP_COMMIT();

    const int NC = LSEQ / 32;
    for (int c = 0; c < NC; ++c) {
        asm volatile("cp.async.wait_group 1;" ::: "memory");
        __syncthreads();
        const float* st = ss + (c % 3) * 4096;
        const float* su = st + 1024;
        const float* sz = st + 2048;
        const float* sbc = st + 3072;
#pragma unroll 4
        for (int s = 0; s < 32; ++s) {
            const float dtc = st[s * 32 + ch];
            const float uc  = su[s * 32 + ch];
            const float2 Bc = *(const float2*)&sbc[s * 32 + sub * 2];
            const float2 Cc = *(const float2*)&sbc[s * 32 + 16 + sub * 2];
            const float dtu = dtc * uc;
            h0 = fmaf(__expf(dtc * a0), h0, dtu * Bc.x);
            h1 = fmaf(__expf(dtc * a1), h1, dtu * Bc.y);
            float y = fmaf(h0, Cc.x, h1 * Cc.y);
            y += __shfl_xor_sync(0xffffffffu, y, 1);
            y += __shfl_xor_sync(0xffffffffu, y, 2);
            y += __shfl_xor_sync(0xffffffffu, y, 4);
            if (sub == 0) {
                const float zc = sz[s * 32 + ch];
                const float sg = zc * (1.0f / (1.0f + __expf(-zc)));
                ybuf[s * 32 + ch] = (y + uc * Dv) * sg;
            }
        }
        __syncthreads();
        // pack ys chunk: 32 steps x 16 channel-pairs = 512 words per plane
        {
            const long long tb = t0 + c * 32;
#pragma unroll
            for (int q = tid; q < 512; q += 256) {
                const int s = q >> 4, c2 = q & 15;
                const long long t = tb + s;
                const int kpg = (dd0 >> 1) + c2;
                const int mt = (int)(t >> 7), row = (int)(t & 127);
                const long long off = (long long)(mt * (DI >> 4) + (kpg >> 3)) * 1024
                                      + a_tile_word(row, kpg & 7);
                uint32_t h, l;
                split_pack_f16(ybuf[s * 32 + 2 * c2], ybuf[s * 32 + 2 * c2 + 1], h, l);
                g_ysh[off] = h; g_ysl[off] = l;
            }
        }
        if (c + 2 < NC) issue(c + 2, (c + 2) % 3);
        CP_COMMIT();
    }
}

// ---------------------------------------------------------------------------
// host launcher (graph-capturable: launches only)
// ---------------------------------------------------------------------------
extern "C" void kernel_launch(void* const* d_in, const int* in_sizes, int n_in,
                              void* d_out, int out_size) {
    const float* x       = (const float*)d_in[0];
    const float* W_in    = (const float*)d_in[1];
    const float* conv_k  = (const float*)d_in[2];
    const float* conv_b  = (const float*)d_in[3];
    const float* W_xproj = (const float*)d_in[4];
    const float* W_dt    = (const float*)d_in[5];
    const float* b_dt    = (const float*)d_in[6];
    const float* A_log   = (const float*)d_in[7];
    const float* Dp      = (const float*)d_in[8];
    const float* W_out   = (const float*)d_in[9];
    float* out = (float*)d_out;

    float *xz, *dt, *pxd, *pout;
    cudaGetSymbolAddress((void**)&xz,   g_xz);
    cudaGetSymbolAddress((void**)&dt,   g_dt);
    cudaGetSymbolAddress((void**)&pxd,  g_pxd);
    cudaGetSymbolAddress((void**)&pout, g_pout);

    uint32_t *xh,*xl,*uh,*ul,*ysh,*ysl,*xdh,*xdl,*wih,*wxh,*wdh,*woh;
    cudaGetSymbolAddress((void**)&xh,  g_xh);  cudaGetSymbolAddress((void**)&xl,  g_xl);
    cudaGetSymbolAddress((void**)&uh,  g_uh);  cudaGetSymbolAddress((void**)&ul,  g_ul);
    cudaGetSymbolAddress((void**)&ysh, g_ysh); cudaGetSymbolAddress((void**)&ysl, g_ysl);
    cudaGetSymbolAddress((void**)&xdh, g_xdh); cudaGetSymbolAddress((void**)&xdl, g_xdl);
    cudaGetSymbolAddress((void**)&wih, g_wih);
    cudaGetSymbolAddress((void**)&wxh, g_wxh);
    cudaGetSymbolAddress((void**)&wdh, g_wdh);
    cudaGetSymbolAddress((void**)&woh, g_woh);

    cudaFuncSetAttribute(bgemm5<0, 0>, cudaFuncAttributeMaxDynamicSharedMemorySize, BG5_SMEM);
    cudaFuncSetAttribute(bgemm5<1, 0>, cudaFuncAttributeMaxDynamicSharedMemorySize, BG5_SMEM);
    cudaFuncSetAttribute(bgemm5<0, 1>, cudaFuncAttributeMaxDynamicSharedMemorySize, BG5_SMEM);
    cudaFuncSetAttribute(scan_kernel,  cudaFuncAttributeMaxDynamicSharedMemorySize, SCAN_SMEM);

    // 0) prep + packs
    prep_kernel<<<(DI * NSTATE) / 256, 256>>>(A_log);
    pack_a_tiled<<<(NT * DM / 2) / 256, 256>>>(x, xh, xl, DM);
    pack_b_tiled<<<((DM / 2) * 2 * DI) / 256, 256>>>(W_in, wih, DM, 2 * DI, 2 * DI);
    pack_b_tiled<<<((DI / 2) * XPNP) / 256, 256>>>(W_xproj, wxh, DI, XPN, XPNP);
    pack_b_tiled<<<((DTR / 2) * DI) / 256, 256>>>(W_dt, wdh, DTR, DI, DI);
    pack_b_tiled<<<((DI / 2) * DM) / 256, 256>>>(W_out, woh, DI, DM, DM);

    // 1) in_proj: xz = x @ W_in           (2048 x 4096, K=1024)
    bgemm5<0, 0><<<dim3(2 * DI / 128, NT / 128, 1), 256, BG5_SMEM>>>(
        xh, xl, wih, xz, 2 * DI, 2 * DI,
        DM / 16, DM / 16, 0, nullptr);

    // 2) depthwise conv + SiLU -> u (fp32 + tiled planes)
    conv_silu_pack<<<(NT * DI / 2) / 256, 256>>>(conv_k, conv_b);

    // 3) xdbl = u @ W_xproj               (2048 x 160, K=2048), split-K 8
    bgemm5<0, 1><<<dim3(2, NT / 128, 8), 256, BG5_SMEM>>>(
        uh, ul, wxh, pxd, XPN, XPN,
        DI / 16, (DI / 8) / 16, (long long)NT * XPN, nullptr);
    reduce8_pack<<<(NT * XPN / 2) / 256, 256>>>();

    // 4) dt = softplus(xdbl[:, :128] @ W_dt + b_dt)   (2048 x 2048, K=128)
    bgemm5<1, 0><<<dim3(DI / 128, NT / 128, 1), 256, BG5_SMEM>>>(
        xdh, xdl, wdh, dt, DI, DI,
        DTR / 16, DTR / 16, 0, b_dt);

    // 5) selective scan (fused skip + gate + ys plane packing)
    scan_kernel<<<dim3(DI / 32, 2), 256, SCAN_SMEM>>>(Dp);

    // 6) out = ys @ W_out                 (2048 x 1024, K=2048), split-K 2
    bgemm5<0, 0><<<dim3(DM / 128, NT / 128, 2), 256, BG5_SMEM>>>(
        ysh, ysl, woh, pout, DM, DM,
        DI / 16, (DI / 2) / 16, (long long)NT * DM, nullptr);
    reduce2_kernel<<<(NT * DM) / 256, 256>>>(out);
}